// round 13
// baseline (speedup 1.0000x reference)
#include <cuda_runtime.h>
#include <cuda_fp16.h>
#include <cstdint>

// Problem constants
#define BB 32
#define LL 1024
#define EE 256
#define HH 256
#define TT 8192
#define KD 768                  // 3*256 im2col contraction
#define MM (BB*LL)              // 32768 rows
#define OUT_OFF (BB*TT*EE)      // duration follows output
#define NCH 12                  // K chunks of 64
#define CHK 64
#define NT 512                  // 16 warps: 4(M) x 4(N)

// Weight blocks: per conv [NCH][64 k][264 n] fp16 (264 = 256 + pad)
#define BROW 264
#define BCH  (CHK*BROW)         // 16896 elems / chunk

__device__ __align__(16) __half g_Xh[MM*EE];    // fp16(x)
__device__ __align__(16) __half g_H1h[MM*HH];   // fp16 LN1 output
__device__ __align__(16) __half g_B1[NCH*BCH];
__device__ __align__(16) __half g_B2[NCH*BCH];
__device__ int g_idx[BB*TT];

// SMEM layout (dynamic): params [0,4096), 3 stages from 4096; epilogue reuses stages
#define SM_STAGE 4096
#define A_HI 0
#define B_HI 18432              // A: 128 rows x 144B
#define STAGE_SZ 52224          // A 18432 + B 33792
#define ASTR 144                // A row stride bytes (64 fp16 + 16 pad)
#define BSTR 528                // B row stride bytes (264 fp16)
#define EPI_STRIDE 264          // epilogue fp32 tile row stride (floats)
#define SMEM_BYTES (4096 + 3*STAGE_SZ)   // 160768 (> epilogue 139264)

__device__ __forceinline__ void ldsm4(uint32_t* r, uint32_t a) {
    asm volatile("ldmatrix.sync.aligned.m8n8.x4.shared.b16 {%0,%1,%2,%3}, [%4];"
        : "=r"(r[0]), "=r"(r[1]), "=r"(r[2]), "=r"(r[3]) : "r"(a));
}
__device__ __forceinline__ void ldsm4t(uint32_t* r, uint32_t a) {
    asm volatile("ldmatrix.sync.aligned.m8n8.x4.trans.shared.b16 {%0,%1,%2,%3}, [%4];"
        : "=r"(r[0]), "=r"(r[1]), "=r"(r[2]), "=r"(r[3]) : "r"(a));
}
__device__ __forceinline__ void mma_f16(float* d, const uint32_t* a, const uint32_t* b) {
    asm volatile(
        "mma.sync.aligned.m16n8k16.row.col.f32.f16.f16.f32 "
        "{%0,%1,%2,%3}, {%4,%5,%6,%7}, {%8,%9}, {%0,%1,%2,%3};"
        : "+f"(d[0]), "+f"(d[1]), "+f"(d[2]), "+f"(d[3])
        : "r"(a[0]), "r"(a[1]), "r"(a[2]), "r"(a[3]), "r"(b[0]), "r"(b[1]));
}
__device__ __forceinline__ uint32_t pack_h2(float x, float y) {
    __half2 h = __floats2half2_rn(x, y);
    return *reinterpret_cast<uint32_t*>(&h);
}
__device__ __forceinline__ void cp16(uint32_t dst, const void* src) {
    asm volatile("cp.async.cg.shared.global [%0], [%1], 16;"
        :: "r"(dst), "l"(src) : "memory");
}
// zero-fill variant: src-size 0 -> smem gets zeros
__device__ __forceinline__ void cp16z(uint32_t dst, const void* src, uint32_t sz) {
    asm volatile("cp.async.cg.shared.global [%0], [%1], 16, %2;"
        :: "r"(dst), "l"(src), "r"(sz) : "memory");
}

// ---------------------------------------------------------------------------
// X fp32 -> fp16 plane
// ---------------------------------------------------------------------------
__global__ void prep_x(const float* __restrict__ X) {
    int i = blockIdx.x * blockDim.x + threadIdx.x;   // one float4 per thread
    float4 v = reinterpret_cast<const float4*>(X)[i];
    uint2 hh;
    hh.x = pack_h2(v.x, v.y);
    hh.y = pack_h2(v.z, v.w);
    reinterpret_cast<uint2*>(g_Xh)[i] = hh;
}

// ---------------------------------------------------------------------------
// Weight prep (one conv): [H,E,K] fp32 -> fp16 in [chunk][k'][n=h]
// ---------------------------------------------------------------------------
__global__ void prep_w(const float* __restrict__ w, __half* __restrict__ dst) {
    int i = blockIdx.x * blockDim.x + threadIdx.x;
    if (i >= HH * KD) return;
    int h = i / KD, kk = i % KD;
    int k = kk / EE, e = kk % EE;
    int c = kk >> 6, kp = kk & 63;
    dst[((size_t)c * CHK + kp) * BROW + h] = __float2half_rn(w[(h * EE + e) * 3 + k]);
}

// ---------------------------------------------------------------------------
// conv-as-GEMM via mma.sync fp16; A and B both cp.async-fed fp16 planes.
// 512 threads: warp grid 4(M) x 4(N), warp tile 32x64. 12 K-chunks of 64.
// mode 0: outHh = fp16(relu(LN(conv+bias)))            [M,256]
// mode 1: outDur = relu(relu(LN(conv+bias)).lw + lb)   fp32 [M]
// ---------------------------------------------------------------------------
__global__ void __launch_bounds__(NT, 1)
conv_mma(const __half* __restrict__ Ain, const __half* __restrict__ WB,
         const float* __restrict__ bias, const float* __restrict__ gamma,
         const float* __restrict__ beta, const float* __restrict__ lw,
         const float* __restrict__ lb, __half* __restrict__ outHh,
         float* __restrict__ outDur, int mode)
{
    extern __shared__ char smem[];
    const int tid = threadIdx.x, lane = tid & 31, wid = tid >> 5;
    const int wm = wid >> 2, wn = wid & 3;       // 4 (M) x 4 (N) warps
    uint32_t sb;
    asm("{ .reg .u64 t; cvta.to.shared.u64 t, %1; cvt.u32.u64 %0, t; }"
        : "=r"(sb) : "l"(smem));

    // params into smem: bias @0, gamma @256, beta @512, lw @768 (floats)
    float* smf = (float*)smem;
    if (tid < 256) {
        smf[tid]       = bias[tid];
        smf[256 + tid] = gamma[tid];
        smf[512 + tid] = beta[tid];
        smf[768 + tid] = lw[tid];
    }

    const int m0 = blockIdx.x * 128;
    const __half* Ab = Ain + (size_t)(m0 >> 10) * (LL * EE);
    const int rowA = tid >> 2, q4 = tid & 3;     // 4 threads/row, 16 elems each
    const int lg = (m0 & (LL - 1)) + rowA;
    const int abase0 = (lg - 1) * EE + q4 * 16;

    float d[2][8][4];
#pragma unroll
    for (int i = 0; i < 2; i++)
#pragma unroll
        for (int j = 0; j < 8; j++)
#pragma unroll
            for (int q = 0; q < 4; q++) d[i][j][q] = 0.f;

    const uint32_t laneA = (uint32_t)((lane & 7) + ((lane >> 3) & 1) * 8) * ASTR
                         + ((lane >> 4) & 1) * 16;
    const uint32_t laneB = (uint32_t)((lane & 7) + ((lane >> 3) & 1) * 8) * BSTR
                         + ((lane >> 4) & 1) * 16;

    auto cpA = [&](int c, int buf) {
        int off = abase0 + c * CHK;
        bool valid = (off >= 0) && (off + 16 <= LL * EE);
        uint32_t sz = valid ? 16u : 0u;
        const char* src = (const char*)(Ab + (valid ? off : 0));
        uint32_t dst = sb + SM_STAGE + (uint32_t)buf * STAGE_SZ
                     + (uint32_t)rowA * ASTR + q4 * 32;
        cp16z(dst,      src,      sz);
        cp16z(dst + 16, src + 16, sz);
    };

    auto cpB = [&](int c, int buf) {
        const char* src = (const char*)(WB + (size_t)c * BCH);
        uint32_t dst = sb + SM_STAGE + (uint32_t)buf * STAGE_SZ + B_HI;
#pragma unroll
        for (int j = 0; j < 4; j++) {
            uint32_t u = tid + NT * j;
            cp16(dst + u * 16, src + (size_t)u * 16);
        }
        uint32_t u = tid + 2048;
        if (u < 2112)
            cp16(dst + u * 16, src + (size_t)u * 16);
    };

    // single-pass MMA, 4 k16 slices per chunk; warp tile 32x64
    auto do_mma = [&](uint32_t stg) {
#pragma unroll
        for (int kb = 0; kb < 4; kb++) {
            uint32_t af[2][4], bh[8][2];
#pragma unroll
            for (int mf = 0; mf < 2; mf++)
                ldsm4(af[mf], stg + A_HI +
                      (uint32_t)(wm * 32 + mf * 16) * ASTR + kb * 32 + laneA);
#pragma unroll
            for (int t = 0; t < 4; t++) {
                uint32_t r[4];
                ldsm4t(r, stg + B_HI + (uint32_t)kb * 16 * BSTR +
                       (uint32_t)(wn * 64 + t * 16) * 2 + laneB);
                bh[2 * t][0] = r[0]; bh[2 * t][1] = r[1];
                bh[2 * t + 1][0] = r[2]; bh[2 * t + 1][1] = r[3];
            }
#pragma unroll
            for (int mf = 0; mf < 2; mf++)
#pragma unroll
                for (int nf = 0; nf < 8; nf++)
                    mma_f16(d[mf][nf], af[mf], bh[nf]);
        }
    };

    // prologue: 2 chunks in flight
    cpA(0, 0); cpB(0, 0);
    asm volatile("cp.async.commit_group;" ::: "memory");
    cpA(1, 1); cpB(1, 1);
    asm volatile("cp.async.commit_group;" ::: "memory");

    for (int c = 0; c < NCH; c++) {
        if (c < NCH - 2)
            asm volatile("cp.async.wait_group 1;" ::: "memory");
        else
            asm volatile("cp.async.wait_group 0;" ::: "memory");
        __syncthreads();
        if (c + 2 < NCH) {
            cpA(c + 2, (c + 2) % 3);
            cpB(c + 2, (c + 2) % 3);
            asm volatile("cp.async.commit_group;" ::: "memory");
        }
        do_mma(sb + SM_STAGE + (uint32_t)(c % 3) * STAGE_SZ);
    }

    // ------- epilogue: acc(+bias) -> smem tile -> per-row LN -------
    __syncthreads();
    float* tile = (float*)(smem + SM_STAGE);
#pragma unroll
    for (int mf = 0; mf < 2; mf++) {
        int r0 = wm * 32 + mf * 16 + (lane >> 2);
#pragma unroll
        for (int nf = 0; nf < 8; nf++) {
            int cc = wn * 64 + nf * 8 + (lane & 3) * 2;
            float b0 = smf[cc], b1 = smf[cc + 1];
            *reinterpret_cast<float2*>(tile + r0 * EPI_STRIDE + cc) =
                make_float2(d[mf][nf][0] + b0, d[mf][nf][1] + b1);
            *reinterpret_cast<float2*>(tile + (r0 + 8) * EPI_STRIDE + cc) =
                make_float2(d[mf][nf][2] + b0, d[mf][nf][3] + b1);
        }
    }
    __syncthreads();

    {
        int r = tid >> 2, qq = tid & 3;          // 4 threads/row, 64 floats each
        const float4* row =
            (const float4*)(tile + r * EPI_STRIDE + qq * 64);
        float sum = 0.f, ss = 0.f;
#pragma unroll
        for (int i = 0; i < 16; i++) {
            float4 v = row[i];
            sum += v.x + v.y + v.z + v.w;
            ss = fmaf(v.x, v.x, ss); ss = fmaf(v.y, v.y, ss);
            ss = fmaf(v.z, v.z, ss); ss = fmaf(v.w, v.w, ss);
        }
        sum += __shfl_xor_sync(0xffffffffu, sum, 1);
        ss  += __shfl_xor_sync(0xffffffffu, ss, 1);
        sum += __shfl_xor_sync(0xffffffffu, sum, 2);
        ss  += __shfl_xor_sync(0xffffffffu, ss, 2);
        float mu  = sum * (1.f / 256.f);
        float inv = rsqrtf(ss * (1.f / 256.f) - mu * mu + 1e-5f);
        const float4* sG  = (const float4*)(smf + 256 + qq * 64);
        const float4* sBe = (const float4*)(smf + 512 + qq * 64);

        if (mode == 0) {
            // store LN+relu output directly as fp16 (A operand of conv2)
            uint4* op = reinterpret_cast<uint4*>(
                outHh + (size_t)(m0 + r) * HH + qq * 64);
#pragma unroll
            for (int i2 = 0; i2 < 8; i2++) {
                float4 v0 = row[2 * i2], v1 = row[2 * i2 + 1];
                float4 g0 = sG[2 * i2], g1 = sG[2 * i2 + 1];
                float4 b0 = sBe[2 * i2], b1 = sBe[2 * i2 + 1];
                float y0 = fmaxf(fmaf((v0.x - mu) * inv, g0.x, b0.x), 0.f);
                float y1 = fmaxf(fmaf((v0.y - mu) * inv, g0.y, b0.y), 0.f);
                float y2 = fmaxf(fmaf((v0.z - mu) * inv, g0.z, b0.z), 0.f);
                float y3 = fmaxf(fmaf((v0.w - mu) * inv, g0.w, b0.w), 0.f);
                float y4 = fmaxf(fmaf((v1.x - mu) * inv, g1.x, b1.x), 0.f);
                float y5 = fmaxf(fmaf((v1.y - mu) * inv, g1.y, b1.y), 0.f);
                float y6 = fmaxf(fmaf((v1.z - mu) * inv, g1.z, b1.z), 0.f);
                float y7 = fmaxf(fmaf((v1.w - mu) * inv, g1.w, b1.w), 0.f);
                uint4 p;
                p.x = pack_h2(y0, y1); p.y = pack_h2(y2, y3);
                p.z = pack_h2(y4, y5); p.w = pack_h2(y6, y7);
                op[i2] = p;
            }
        } else {
            const float4* sLw = (const float4*)(smf + 768 + qq * 64);
            float dot = 0.f;
#pragma unroll
            for (int i = 0; i < 16; i++) {
                float4 v = row[i], g = sG[i], be = sBe[i], w = sLw[i];
                dot = fmaf(fmaxf(fmaf((v.x - mu) * inv, g.x, be.x), 0.f), w.x, dot);
                dot = fmaf(fmaxf(fmaf((v.y - mu) * inv, g.y, be.y), 0.f), w.y, dot);
                dot = fmaf(fmaxf(fmaf((v.z - mu) * inv, g.z, be.z), 0.f), w.z, dot);
                dot = fmaf(fmaxf(fmaf((v.w - mu) * inv, g.w, be.w), 0.f), w.w, dot);
            }
            dot += __shfl_xor_sync(0xffffffffu, dot, 1);
            dot += __shfl_xor_sync(0xffffffffu, dot, 2);
            if (qq == 0) outDur[m0 + r] = fmaxf(dot + lb[0], 0.f);
        }
    }
}

// ---------------------------------------------------------------------------
// Per-batch cumsum of target + searchsorted(right) -> g_idx[b,t] (-1 = zero)
// ---------------------------------------------------------------------------
__global__ void scan_idx(const int* __restrict__ target) {
    __shared__ int cum[LL];
    __shared__ int ps[256];
    int b = blockIdx.x;
    int tid = threadIdx.x;
    const int* tb = target + b * LL;
    int v[4], s = 0;
#pragma unroll
    for (int i = 0; i < 4; i++) { v[i] = tb[tid * 4 + i]; s += v[i]; }
    ps[tid] = s;
    __syncthreads();
    for (int o = 1; o < 256; o <<= 1) {
        int t = (tid >= o) ? ps[tid - o] : 0;
        __syncthreads();
        ps[tid] += t;
        __syncthreads();
    }
    int run = ps[tid] - s;
#pragma unroll
    for (int i = 0; i < 4; i++) { run += v[i]; cum[tid * 4 + i] = run; }
    __syncthreads();
    int total = cum[LL - 1];
    for (int t = tid; t < TT; t += 256) {
        int r = -1;
        if (t < total) {
            int lo = 0, hi = LL;
            while (lo < hi) {
                int mid = (lo + hi) >> 1;
                if (cum[mid] <= t) lo = mid + 1; else hi = mid;
            }
            r = lo < (LL - 1) ? lo : (LL - 1);
        }
        g_idx[b * TT + t] = r;
    }
}

// ---------------------------------------------------------------------------
// Gather/zero-fill: out[b,t,:] = (idx>=0) ? x[b,idx,:] : 0
// ---------------------------------------------------------------------------
__global__ void copy_out(const float* __restrict__ X, float* __restrict__ out) {
    int tid  = threadIdx.x;
    int rt   = blockIdx.x * 4 + (tid >> 6);
    int lane = tid & 63;
    int b = rt >> 13;
    int j = g_idx[rt];
    float4 val = make_float4(0.f, 0.f, 0.f, 0.f);
    if (j >= 0)
        val = *reinterpret_cast<const float4*>(X + (b * LL + j) * EE + lane * 4);
    *reinterpret_cast<float4*>(out + (size_t)rt * EE + lane * 4) = val;
}

// ---------------------------------------------------------------------------
extern "C" void kernel_launch(void* const* d_in, const int* in_sizes, int n_in,
                              void* d_out, int out_size) {
    const float* x      = (const float*)d_in[0];
    const int*   target = (const int*)  d_in[1];
    const float* c1w = (const float*)d_in[3];
    const float* c1b = (const float*)d_in[4];
    const float* g1  = (const float*)d_in[5];
    const float* b1  = (const float*)d_in[6];
    const float* c2w = (const float*)d_in[7];
    const float* c2b = (const float*)d_in[8];
    const float* g2  = (const float*)d_in[9];
    const float* b2  = (const float*)d_in[10];
    const float* lw  = (const float*)d_in[11];
    const float* lb  = (const float*)d_in[12];

    float* out = (float*)d_out;
    float* dur = out + OUT_OFF;

    __half *Xh, *H1h, *B1, *B2;
    cudaGetSymbolAddress((void**)&Xh,  g_Xh);
    cudaGetSymbolAddress((void**)&H1h, g_H1h);
    cudaGetSymbolAddress((void**)&B1,  g_B1);
    cudaGetSymbolAddress((void**)&B2,  g_B2);

    cudaFuncSetAttribute(conv_mma, cudaFuncAttributeMaxDynamicSharedMemorySize,
                         SMEM_BYTES);

    // Side stream + events for fork/join inside graph capture.
    static cudaStream_t s_side = nullptr;
    static cudaEvent_t  ev_fork = nullptr, ev_px = nullptr,
                        ev_pw2 = nullptr, ev_join = nullptr;
    if (s_side == nullptr) {
        cudaStreamCreateWithFlags(&s_side, cudaStreamNonBlocking);
        cudaEventCreateWithFlags(&ev_fork, cudaEventDisableTiming);
        cudaEventCreateWithFlags(&ev_px,   cudaEventDisableTiming);
        cudaEventCreateWithFlags(&ev_pw2,  cudaEventDisableTiming);
        cudaEventCreateWithFlags(&ev_join, cudaEventDisableTiming);
    }

    cudaEventRecord(ev_fork, 0);
    cudaStreamWaitEvent(s_side, ev_fork, 0);

    // side: prep_x (needed by conv1), prep B2 (needed by conv2), regulate path
    prep_x<<<MM * EE / 4 / 256, 256, 0, s_side>>>(x);
    cudaEventRecord(ev_px, s_side);
    prep_w<<<(HH * KD + 255) / 256, 256, 0, s_side>>>(c2w, B2);
    cudaEventRecord(ev_pw2, s_side);
    scan_idx<<<BB, 256, 0, s_side>>>(target);
    copy_out<<<(BB * TT) / 4, 256, 0, s_side>>>(x, out);
    cudaEventRecord(ev_join, s_side);

    // main: prep B1 runs concurrent with prep_x, then the two convs
    prep_w<<<(HH * KD + 255) / 256, 256>>>(c1w, B1);
    cudaStreamWaitEvent(0, ev_px, 0);
    conv_mma<<<MM / 128, NT, SMEM_BYTES>>>(Xh, B1, c1b, g1, b1, lw, lb,
                                           H1h, nullptr, 0);
    cudaStreamWaitEvent(0, ev_pw2, 0);
    conv_mma<<<MM / 128, NT, SMEM_BYTES>>>(H1h, B2, c2b, g2, b2, lw, lb,
                                           nullptr, dur, 1);

    // join
    cudaStreamWaitEvent(0, ev_join, 0);
}

// round 14
// speedup vs baseline: 1.0979x; 1.0979x over previous
#include <cuda_runtime.h>
#include <cuda_fp16.h>
#include <cstdint>

// Problem constants
#define BB 32
#define LL 1024
#define EE 256
#define HH 256
#define TT 8192
#define KD 768                  // 3*256 im2col contraction
#define MM (BB*LL)              // 32768 rows
#define OUT_OFF (BB*TT*EE)      // duration follows output
#define NCH 12                  // K chunks of 64
#define CHK 64
#define NTILES (MM/128)         // 256 M-tiles per conv

// Weight blocks: per conv [NCH][64 k][264 n] fp16 (264 = 256 + pad)
#define BROW 264
#define BCH  (CHK*BROW)         // 16896 elems / chunk

__device__ __align__(16) __half g_Xh[MM*EE];    // fp16(x)
__device__ __align__(16) __half g_H1h[MM*HH];   // fp16 LN1 output
__device__ __align__(16) __half g_B1[NCH*BCH];
__device__ __align__(16) __half g_B2[NCH*BCH];
__device__ int g_flag[NTILES];                  // conv1 tile completion flags
__device__ int g_idx[BB*TT];

// SMEM layout (dynamic): params [0,4096), 3 stages from 4096; epilogue reuses stages
#define SM_STAGE 4096
#define A_HI 0
#define B_HI 18432              // A: 128 rows x 144B
#define STAGE_SZ 52224          // A 18432 + B 33792
#define ASTR 144                // A row stride bytes (64 fp16 + 16 pad)
#define BSTR 528                // B row stride bytes (264 fp16)
#define EPI_STRIDE 264          // epilogue fp32 tile row stride (floats)
#define SMEM_BYTES (4096 + 3*STAGE_SZ)   // 160768 (> epilogue 139264)

__device__ __forceinline__ void ldsm4(uint32_t* r, uint32_t a) {
    asm volatile("ldmatrix.sync.aligned.m8n8.x4.shared.b16 {%0,%1,%2,%3}, [%4];"
        : "=r"(r[0]), "=r"(r[1]), "=r"(r[2]), "=r"(r[3]) : "r"(a));
}
__device__ __forceinline__ void ldsm4t(uint32_t* r, uint32_t a) {
    asm volatile("ldmatrix.sync.aligned.m8n8.x4.trans.shared.b16 {%0,%1,%2,%3}, [%4];"
        : "=r"(r[0]), "=r"(r[1]), "=r"(r[2]), "=r"(r[3]) : "r"(a));
}
__device__ __forceinline__ void mma_f16(float* d, const uint32_t* a, const uint32_t* b) {
    asm volatile(
        "mma.sync.aligned.m16n8k16.row.col.f32.f16.f16.f32 "
        "{%0,%1,%2,%3}, {%4,%5,%6,%7}, {%8,%9}, {%0,%1,%2,%3};"
        : "+f"(d[0]), "+f"(d[1]), "+f"(d[2]), "+f"(d[3])
        : "r"(a[0]), "r"(a[1]), "r"(a[2]), "r"(a[3]), "r"(b[0]), "r"(b[1]));
}
__device__ __forceinline__ uint32_t pack_h2(float x, float y) {
    __half2 h = __floats2half2_rn(x, y);
    return *reinterpret_cast<uint32_t*>(&h);
}
__device__ __forceinline__ void cp16(uint32_t dst, const void* src) {
    asm volatile("cp.async.cg.shared.global [%0], [%1], 16;"
        :: "r"(dst), "l"(src) : "memory");
}
// zero-fill variant: src-size 0 -> smem gets zeros
__device__ __forceinline__ void cp16z(uint32_t dst, const void* src, uint32_t sz) {
    asm volatile("cp.async.cg.shared.global [%0], [%1], 16, %2;"
        :: "r"(dst), "l"(src), "r"(sz) : "memory");
}

// ---------------------------------------------------------------------------
__global__ void zero_flags() { g_flag[threadIdx.x] = 0; }

// X fp32 -> fp16 plane
__global__ void prep_x(const float* __restrict__ X) {
    int i = blockIdx.x * blockDim.x + threadIdx.x;   // one float4 per thread
    float4 v = reinterpret_cast<const float4*>(X)[i];
    uint2 hh;
    hh.x = pack_h2(v.x, v.y);
    hh.y = pack_h2(v.z, v.w);
    reinterpret_cast<uint2*>(g_Xh)[i] = hh;
}

// Weight prep (one conv): [H,E,K] fp32 -> fp16 in [chunk][k'][n=h]
__global__ void prep_w(const float* __restrict__ w, __half* __restrict__ dst) {
    int i = blockIdx.x * blockDim.x + threadIdx.x;
    if (i >= HH * KD) return;
    int h = i / KD, kk = i % KD;
    int k = kk / EE, e = kk % EE;
    int c = kk >> 6, kp = kk & 63;
    dst[((size_t)c * CHK + kp) * BROW + h] = __float2half_rn(w[(h * EE + e) * 3 + k]);
}

// ---------------------------------------------------------------------------
// Fused conv1+conv2 via inter-block flags.
// blocks [0,256): conv1 tile = bid   -> H1h fp16, signal g_flag[tile]
// blocks [256,512): conv2 tile = bid-256, waits flags t-1,t,t+1 (batch-clamped)
//                  -> duration
// 256 threads: warp grid 2(M) x 4(N), warp tile 64x64. 12 K-chunks of 64.
// ---------------------------------------------------------------------------
__global__ void __launch_bounds__(256, 1)
conv_fused(const float* __restrict__ c1b, const float* __restrict__ g1,
           const float* __restrict__ b1, const float* __restrict__ c2b,
           const float* __restrict__ g2, const float* __restrict__ b2,
           const float* __restrict__ lw, const float* __restrict__ lb,
           float* __restrict__ outDur)
{
    extern __shared__ char smem[];
    const int tid = threadIdx.x, lane = tid & 31, wid = tid >> 5;
    const int wm = wid >> 2, wn = wid & 3;       // 2 (M) x 4 (N) warps
    const bool isC2 = blockIdx.x >= NTILES;
    const int tile = blockIdx.x & (NTILES - 1);
    uint32_t sb;
    asm("{ .reg .u64 t; cvta.to.shared.u64 t, %1; cvt.u32.u64 %0, t; }"
        : "=r"(sb) : "l"(smem));

    const __half* Ain = isC2 ? g_H1h : g_Xh;
    const __half* WB  = isC2 ? g_B2  : g_B1;
    const float* bias = isC2 ? c2b : c1b;
    const float* gam  = isC2 ? g2  : g1;
    const float* bet  = isC2 ? b2  : b1;

    // params into smem: bias @0, gamma @256, beta @512, lw @768 (floats)
    float* smf = (float*)smem;
    smf[tid]       = bias[tid];
    smf[256 + tid] = gam[tid];
    smf[512 + tid] = bet[tid];
    smf[768 + tid] = lw[tid];

    // conv2: wait for producer tiles (t-1, t, t+1 within this tile's batch)
    if (isC2) {
        if (tid == 0) {
            int lo = (tile & 7) ? tile - 1 : tile;          // 8 tiles per batch
            int hi = ((tile & 7) == 7) ? tile : tile + 1;
            while (atomicAdd(&g_flag[lo],   0) == 0) __nanosleep(64);
            while (atomicAdd(&g_flag[tile], 0) == 0) __nanosleep(64);
            while (atomicAdd(&g_flag[hi],   0) == 0) __nanosleep(64);
            __threadfence();
        }
        __syncthreads();
    }

    const int m0 = tile * 128;
    const __half* Ab = Ain + (size_t)(m0 >> 10) * (LL * EE);
    const int rowA = tid >> 1, half = tid & 1;
    const int lg = (m0 & (LL - 1)) + rowA;
    const int abase0 = (lg - 1) * EE + half * 32;   // elems; 32 elems per thread

    float d[4][8][4];
#pragma unroll
    for (int i = 0; i < 4; i++)
#pragma unroll
        for (int j = 0; j < 8; j++)
#pragma unroll
            for (int q = 0; q < 4; q++) d[i][j][q] = 0.f;

    const uint32_t laneA = (uint32_t)((lane & 7) + ((lane >> 3) & 1) * 8) * ASTR
                         + ((lane >> 4) & 1) * 16;
    const uint32_t laneB = (uint32_t)((lane & 7) + ((lane >> 3) & 1) * 8) * BSTR
                         + ((lane >> 4) & 1) * 16;

    auto cpA = [&](int c, int buf) {
        int off = abase0 + c * CHK;
        bool valid = (off >= 0) && (off + 32 <= LL * EE);
        uint32_t sz = valid ? 16u : 0u;
        const char* src = (const char*)(Ab + (valid ? off : 0));
        uint32_t dst = sb + SM_STAGE + (uint32_t)buf * STAGE_SZ
                     + (uint32_t)rowA * ASTR + half * 64;
        cp16z(dst,      src,      sz);
        cp16z(dst + 16, src + 16, sz);
        cp16z(dst + 32, src + 32, sz);
        cp16z(dst + 48, src + 48, sz);
    };

    auto cpB = [&](int c, int buf) {
        const char* src = (const char*)(WB + (size_t)c * BCH);
        uint32_t dst = sb + SM_STAGE + (uint32_t)buf * STAGE_SZ + B_HI;
#pragma unroll
        for (int j = 0; j < 8; j++) {
            uint32_t u = tid + 256 * j;
            cp16(dst + u * 16, src + (size_t)u * 16);
        }
        uint32_t u = tid + 2048;
        if (u < 2112)
            cp16(dst + u * 16, src + (size_t)u * 16);
    };

    // single-pass MMA, 4 k16 slices per chunk
    auto do_mma = [&](uint32_t stg) {
#pragma unroll
        for (int kb = 0; kb < 4; kb++) {
            uint32_t af[4][4], bh[8][2];
#pragma unroll
            for (int mf = 0; mf < 4; mf++)
                ldsm4(af[mf], stg + A_HI +
                      (uint32_t)(wm * 64 + mf * 16) * ASTR + kb * 32 + laneA);
#pragma unroll
            for (int t = 0; t < 4; t++) {
                uint32_t r[4];
                ldsm4t(r, stg + B_HI + (uint32_t)kb * 16 * BSTR +
                       (uint32_t)(wn * 64 + t * 16) * 2 + laneB);
                bh[2 * t][0] = r[0]; bh[2 * t][1] = r[1];
                bh[2 * t + 1][0] = r[2]; bh[2 * t + 1][1] = r[3];
            }
#pragma unroll
            for (int mf = 0; mf < 4; mf++)
#pragma unroll
                for (int nf = 0; nf < 8; nf++)
                    mma_f16(d[mf][nf], af[mf], bh[nf]);
        }
    };

    // prologue: 2 chunks in flight
    cpA(0, 0); cpB(0, 0);
    asm volatile("cp.async.commit_group;" ::: "memory");
    cpA(1, 1); cpB(1, 1);
    asm volatile("cp.async.commit_group;" ::: "memory");

    for (int c = 0; c < NCH; c++) {
        if (c < NCH - 2)
            asm volatile("cp.async.wait_group 1;" ::: "memory");
        else
            asm volatile("cp.async.wait_group 0;" ::: "memory");
        __syncthreads();
        if (c + 2 < NCH) {
            cpA(c + 2, (c + 2) % 3);
            cpB(c + 2, (c + 2) % 3);
            asm volatile("cp.async.commit_group;" ::: "memory");
        }
        do_mma(sb + SM_STAGE + (uint32_t)(c % 3) * STAGE_SZ);
    }

    // ------- epilogue: acc(+bias) -> smem tile -> per-row LN -------
    __syncthreads();
    float* tile_f = (float*)(smem + SM_STAGE);
#pragma unroll
    for (int mf = 0; mf < 4; mf++) {
        int r0 = wm * 64 + mf * 16 + (lane >> 2);
#pragma unroll
        for (int nf = 0; nf < 8; nf++) {
            int cc = wn * 64 + nf * 8 + (lane & 3) * 2;
            float b0 = smf[cc], b1v = smf[cc + 1];
            *reinterpret_cast<float2*>(tile_f + r0 * EPI_STRIDE + cc) =
                make_float2(d[mf][nf][0] + b0, d[mf][nf][1] + b1v);
            *reinterpret_cast<float2*>(tile_f + (r0 + 8) * EPI_STRIDE + cc) =
                make_float2(d[mf][nf][2] + b0, d[mf][nf][3] + b1v);
        }
    }
    __syncthreads();

    {
        int r = tid >> 1, h2 = tid & 1;
        const float4* row =
            (const float4*)(tile_f + r * EPI_STRIDE + h2 * 128);
        float sum = 0.f, ss = 0.f;
#pragma unroll
        for (int i = 0; i < 32; i++) {
            float4 v = row[i];
            sum += v.x + v.y + v.z + v.w;
            ss = fmaf(v.x, v.x, ss); ss = fmaf(v.y, v.y, ss);
            ss = fmaf(v.z, v.z, ss); ss = fmaf(v.w, v.w, ss);
        }
        sum += __shfl_xor_sync(0xffffffffu, sum, 1);
        ss  += __shfl_xor_sync(0xffffffffu, ss, 1);
        float mu  = sum * (1.f / 256.f);
        float inv = rsqrtf(ss * (1.f / 256.f) - mu * mu + 1e-5f);
        const float4* sG  = (const float4*)(smf + 256 + h2 * 128);
        const float4* sBe = (const float4*)(smf + 512 + h2 * 128);

        if (!isC2) {
            // store LN+relu output directly as fp16 (A operand of conv2)
            uint4* op = reinterpret_cast<uint4*>(
                g_H1h + (size_t)(m0 + r) * HH + h2 * 128);
#pragma unroll
            for (int i2 = 0; i2 < 16; i2++) {
                float4 v0 = row[2 * i2], v1 = row[2 * i2 + 1];
                float4 g0 = sG[2 * i2], g1v = sG[2 * i2 + 1];
                float4 b0 = sBe[2 * i2], b1v = sBe[2 * i2 + 1];
                float y0 = fmaxf(fmaf((v0.x - mu) * inv, g0.x, b0.x), 0.f);
                float y1 = fmaxf(fmaf((v0.y - mu) * inv, g0.y, b0.y), 0.f);
                float y2 = fmaxf(fmaf((v0.z - mu) * inv, g0.z, b0.z), 0.f);
                float y3 = fmaxf(fmaf((v0.w - mu) * inv, g0.w, b0.w), 0.f);
                float y4 = fmaxf(fmaf((v1.x - mu) * inv, g1v.x, b1v.x), 0.f);
                float y5 = fmaxf(fmaf((v1.y - mu) * inv, g1v.y, b1v.y), 0.f);
                float y6 = fmaxf(fmaf((v1.z - mu) * inv, g1v.z, b1v.z), 0.f);
                float y7 = fmaxf(fmaf((v1.w - mu) * inv, g1v.w, b1v.w), 0.f);
                uint4 p;
                p.x = pack_h2(y0, y1); p.y = pack_h2(y2, y3);
                p.z = pack_h2(y4, y5); p.w = pack_h2(y6, y7);
                op[i2] = p;
            }
        } else {
            const float4* sLw = (const float4*)(smf + 768 + h2 * 128);
            float dot = 0.f;
#pragma unroll
            for (int i = 0; i < 32; i++) {
                float4 v = row[i], g = sG[i], be = sBe[i], w = sLw[i];
                dot = fmaf(fmaxf(fmaf((v.x - mu) * inv, g.x, be.x), 0.f), w.x, dot);
                dot = fmaf(fmaxf(fmaf((v.y - mu) * inv, g.y, be.y), 0.f), w.y, dot);
                dot = fmaf(fmaxf(fmaf((v.z - mu) * inv, g.z, be.z), 0.f), w.z, dot);
                dot = fmaf(fmaxf(fmaf((v.w - mu) * inv, g.w, be.w), 0.f), w.w, dot);
            }
            dot += __shfl_xor_sync(0xffffffffu, dot, 1);
            if (h2 == 0) outDur[m0 + r] = fmaxf(dot + lb[0], 0.f);
        }
    }

    // conv1: publish tile completion
    if (!isC2) {
        __syncthreads();
        if (tid == 0) {
            __threadfence();
            atomicExch(&g_flag[tile], 1);
        }
    }
}

// ---------------------------------------------------------------------------
// Per-batch cumsum of target + searchsorted(right) -> g_idx[b,t] (-1 = zero)
// ---------------------------------------------------------------------------
__global__ void scan_idx(const int* __restrict__ target) {
    __shared__ int cum[LL];
    __shared__ int ps[256];
    int b = blockIdx.x;
    int tid = threadIdx.x;
    const int* tb = target + b * LL;
    int v[4], s = 0;
#pragma unroll
    for (int i = 0; i < 4; i++) { v[i] = tb[tid * 4 + i]; s += v[i]; }
    ps[tid] = s;
    __syncthreads();
    for (int o = 1; o < 256; o <<= 1) {
        int t = (tid >= o) ? ps[tid - o] : 0;
        __syncthreads();
        ps[tid] += t;
        __syncthreads();
    }
    int run = ps[tid] - s;
#pragma unroll
    for (int i = 0; i < 4; i++) { run += v[i]; cum[tid * 4 + i] = run; }
    __syncthreads();
    int total = cum[LL - 1];
    for (int t = tid; t < TT; t += 256) {
        int r = -1;
        if (t < total) {
            int lo = 0, hi = LL;
            while (lo < hi) {
                int mid = (lo + hi) >> 1;
                if (cum[mid] <= t) lo = mid + 1; else hi = mid;
            }
            r = lo < (LL - 1) ? lo : (LL - 1);
        }
        g_idx[b * TT + t] = r;
    }
}

// ---------------------------------------------------------------------------
// Gather/zero-fill: out[b,t,:] = (idx>=0) ? x[b,idx,:] : 0
// ---------------------------------------------------------------------------
__global__ void copy_out(const float* __restrict__ X, float* __restrict__ out) {
    int tid  = threadIdx.x;
    int rt   = blockIdx.x * 4 + (tid >> 6);
    int lane = tid & 63;
    int b = rt >> 13;
    int j = g_idx[rt];
    float4 val = make_float4(0.f, 0.f, 0.f, 0.f);
    if (j >= 0)
        val = *reinterpret_cast<const float4*>(X + (b * LL + j) * EE + lane * 4);
    *reinterpret_cast<float4*>(out + (size_t)rt * EE + lane * 4) = val;
}

// ---------------------------------------------------------------------------
extern "C" void kernel_launch(void* const* d_in, const int* in_sizes, int n_in,
                              void* d_out, int out_size) {
    const float* x      = (const float*)d_in[0];
    const int*   target = (const int*)  d_in[1];
    const float* c1w = (const float*)d_in[3];
    const float* c1b = (const float*)d_in[4];
    const float* g1  = (const float*)d_in[5];
    const float* b1  = (const float*)d_in[6];
    const float* c2w = (const float*)d_in[7];
    const float* c2b = (const float*)d_in[8];
    const float* g2  = (const float*)d_in[9];
    const float* b2  = (const float*)d_in[10];
    const float* lw  = (const float*)d_in[11];
    const float* lb  = (const float*)d_in[12];

    float* out = (float*)d_out;
    float* dur = out + OUT_OFF;

    __half *B1, *B2;
    cudaGetSymbolAddress((void**)&B1, g_B1);
    cudaGetSymbolAddress((void**)&B2, g_B2);

    cudaFuncSetAttribute(conv_fused, cudaFuncAttributeMaxDynamicSharedMemorySize,
                         SMEM_BYTES);

    // Side stream + events for fork/join inside graph capture.
    static cudaStream_t s_side = nullptr;
    static cudaEvent_t  ev_fork = nullptr, ev_px = nullptr,
                        ev_pw2 = nullptr, ev_join = nullptr;
    if (s_side == nullptr) {
        cudaStreamCreateWithFlags(&s_side, cudaStreamNonBlocking);
        cudaEventCreateWithFlags(&ev_fork, cudaEventDisableTiming);
        cudaEventCreateWithFlags(&ev_px,   cudaEventDisableTiming);
        cudaEventCreateWithFlags(&ev_pw2,  cudaEventDisableTiming);
        cudaEventCreateWithFlags(&ev_join, cudaEventDisableTiming);
    }

    cudaEventRecord(ev_fork, 0);
    cudaStreamWaitEvent(s_side, ev_fork, 0);

    // side: prep_x, prep B2, regulate path
    prep_x<<<MM * EE / 4 / 256, 256, 0, s_side>>>(x);
    cudaEventRecord(ev_px, s_side);
    prep_w<<<(HH * KD + 255) / 256, 256, 0, s_side>>>(c2w, B2);
    cudaEventRecord(ev_pw2, s_side);
    scan_idx<<<BB, 256, 0, s_side>>>(target);
    copy_out<<<(BB * TT) / 4, 256, 0, s_side>>>(x, out);
    cudaEventRecord(ev_join, s_side);

    // main: flag reset + prep B1 (concurrent with side preps), then fused convs
    zero_flags<<<1, NTILES>>>();
    prep_w<<<(HH * KD + 255) / 256, 256>>>(c1w, B1);
    cudaStreamWaitEvent(0, ev_px, 0);
    cudaStreamWaitEvent(0, ev_pw2, 0);
    conv_fused<<<2 * NTILES, 256, SMEM_BYTES>>>(c1b, g1, b1, c2b, g2, b2,
                                                lw, lb, dur);

    // join
    cudaStreamWaitEvent(0, ev_join, 0);
}

// round 15
// speedup vs baseline: 1.1028x; 1.0045x over previous
#include <cuda_runtime.h>
#include <cuda_fp16.h>
#include <cstdint>

// Problem constants
#define BB 32
#define LL 1024
#define EE 256
#define HH 256
#define TT 8192
#define KD 768                  // 3*256 im2col contraction
#define MM (BB*LL)              // 32768 rows
#define OUT_OFF (BB*TT*EE)      // duration follows output
#define NCH 12                  // K chunks of 64
#define CHK 64
#define NTILES (MM/128)         // 256 M-tiles per conv

// Weight blocks: per conv [NCH][64 k][264 n] fp16 (264 = 256 + pad)
#define BROW 264
#define BCH  (CHK*BROW)         // 16896 elems / chunk

__device__ __align__(16) __half g_Xh[MM*EE];    // fp16(x)
__device__ __align__(16) __half g_H1h[MM*HH];   // fp16 LN1 output
__device__ __align__(16) __half g_B1[NCH*BCH];
__device__ __align__(16) __half g_B2[NCH*BCH];
__device__ int g_flag[NTILES];                  // conv1 tile completion flags
__device__ int g_idx[BB*TT];

// SMEM layout (dynamic): params [0,4096), 4 stages from 4096; epilogue reuses stages
#define SM_STAGE 4096
#define A_HI 0
#define B_HI 18432              // A: 128 rows x 144B
#define STAGE_SZ 52224          // A 18432 + B 33792
#define ASTR 144                // A row stride bytes (64 fp16 + 16 pad)
#define BSTR 528                // B row stride bytes (264 fp16)
#define EPI_STRIDE 264          // epilogue fp32 tile row stride (floats)
#define SMEM_BYTES (4096 + 4*STAGE_SZ)   // 212992 (> epilogue 139264; < 227KB)

__device__ __forceinline__ void ldsm4(uint32_t* r, uint32_t a) {
    asm volatile("ldmatrix.sync.aligned.m8n8.x4.shared.b16 {%0,%1,%2,%3}, [%4];"
        : "=r"(r[0]), "=r"(r[1]), "=r"(r[2]), "=r"(r[3]) : "r"(a));
}
__device__ __forceinline__ void ldsm4t(uint32_t* r, uint32_t a) {
    asm volatile("ldmatrix.sync.aligned.m8n8.x4.trans.shared.b16 {%0,%1,%2,%3}, [%4];"
        : "=r"(r[0]), "=r"(r[1]), "=r"(r[2]), "=r"(r[3]) : "r"(a));
}
__device__ __forceinline__ void mma_f16(float* d, const uint32_t* a, const uint32_t* b) {
    asm volatile(
        "mma.sync.aligned.m16n8k16.row.col.f32.f16.f16.f32 "
        "{%0,%1,%2,%3}, {%4,%5,%6,%7}, {%8,%9}, {%0,%1,%2,%3};"
        : "+f"(d[0]), "+f"(d[1]), "+f"(d[2]), "+f"(d[3])
        : "r"(a[0]), "r"(a[1]), "r"(a[2]), "r"(a[3]), "r"(b[0]), "r"(b[1]));
}
__device__ __forceinline__ uint32_t pack_h2(float x, float y) {
    __half2 h = __floats2half2_rn(x, y);
    return *reinterpret_cast<uint32_t*>(&h);
}
__device__ __forceinline__ void cp16(uint32_t dst, const void* src) {
    asm volatile("cp.async.cg.shared.global [%0], [%1], 16;"
        :: "r"(dst), "l"(src) : "memory");
}
// zero-fill variant: src-size 0 -> smem gets zeros
__device__ __forceinline__ void cp16z(uint32_t dst, const void* src, uint32_t sz) {
    asm volatile("cp.async.cg.shared.global [%0], [%1], 16, %2;"
        :: "r"(dst), "l"(src), "r"(sz) : "memory");
}

// ---------------------------------------------------------------------------
// X fp32 -> fp16 plane
__global__ void prep_x(const float* __restrict__ X) {
    int i = blockIdx.x * blockDim.x + threadIdx.x;   // one float4 per thread
    float4 v = reinterpret_cast<const float4*>(X)[i];
    uint2 hh;
    hh.x = pack_h2(v.x, v.y);
    hh.y = pack_h2(v.z, v.w);
    reinterpret_cast<uint2*>(g_Xh)[i] = hh;
}

// Weight prep (one conv): [H,E,K] fp32 -> fp16 in [chunk][k'][n=h].
// zero_flags!=0: block 0 also resets the conv1 completion flags.
__global__ void prep_w(const float* __restrict__ w, __half* __restrict__ dst,
                       int zero_flags) {
    int i = blockIdx.x * blockDim.x + threadIdx.x;
    if (zero_flags && blockIdx.x == 0 && threadIdx.x < NTILES)
        g_flag[threadIdx.x] = 0;
    if (i >= HH * KD) return;
    int h = i / KD, kk = i % KD;
    int k = kk / EE, e = kk % EE;
    int c = kk >> 6, kp = kk & 63;
    dst[((size_t)c * CHK + kp) * BROW + h] = __float2half_rn(w[(h * EE + e) * 3 + k]);
}

// ---------------------------------------------------------------------------
// Fused conv1+conv2 via inter-block flags.
// blocks [0,256): conv1 tile = bid   -> H1h fp16, signal g_flag[tile]
// blocks [256,512): conv2 tile = bid-256, waits flags t-1,t,t+1 (batch-clamped)
//                  -> duration
// 256 threads: warp grid 2(M) x 4(N), warp tile 64x64. 12 K-chunks of 64.
// 4-stage cp.async pipeline, 3 groups in flight.
// ---------------------------------------------------------------------------
__global__ void __launch_bounds__(256, 1)
conv_fused(const float* __restrict__ c1b, const float* __restrict__ g1,
           const float* __restrict__ b1, const float* __restrict__ c2b,
           const float* __restrict__ g2, const float* __restrict__ b2,
           const float* __restrict__ lw, const float* __restrict__ lb,
           float* __restrict__ outDur)
{
    extern __shared__ char smem[];
    const int tid = threadIdx.x, lane = tid & 31, wid = tid >> 5;
    const int wm = wid >> 2, wn = wid & 3;       // 2 (M) x 4 (N) warps
    const bool isC2 = blockIdx.x >= NTILES;
    const int tile = blockIdx.x & (NTILES - 1);
    uint32_t sb;
    asm("{ .reg .u64 t; cvta.to.shared.u64 t, %1; cvt.u32.u64 %0, t; }"
        : "=r"(sb) : "l"(smem));

    const __half* Ain = isC2 ? g_H1h : g_Xh;
    const __half* WB  = isC2 ? g_B2  : g_B1;
    const float* bias = isC2 ? c2b : c1b;
    const float* gam  = isC2 ? g2  : g1;
    const float* bet  = isC2 ? b2  : b1;

    // params into smem: bias @0, gamma @256, beta @512, lw @768 (floats)
    float* smf = (float*)smem;
    smf[tid]       = bias[tid];
    smf[256 + tid] = gam[tid];
    smf[512 + tid] = bet[tid];
    smf[768 + tid] = lw[tid];

    // conv2: wait for producer tiles (t-1, t, t+1 within this tile's batch),
    // 3 threads poll in parallel.
    if (isC2) {
        if (tid < 3) {
            int lo = (tile & 7) ? tile - 1 : tile;          // 8 tiles per batch
            int hi = ((tile & 7) == 7) ? tile : tile + 1;
            int t = (tid == 0) ? lo : ((tid == 1) ? tile : hi);
            while (atomicAdd(&g_flag[t], 0) == 0) __nanosleep(64);
            __threadfence();
        }
        __syncthreads();
    }

    const int m0 = tile * 128;
    const __half* Ab = Ain + (size_t)(m0 >> 10) * (LL * EE);
    const int rowA = tid >> 1, half = tid & 1;
    const int lg = (m0 & (LL - 1)) + rowA;
    const int abase0 = (lg - 1) * EE + half * 32;   // elems; 32 elems per thread

    float d[4][8][4];
#pragma unroll
    for (int i = 0; i < 4; i++)
#pragma unroll
        for (int j = 0; j < 8; j++)
#pragma unroll
            for (int q = 0; q < 4; q++) d[i][j][q] = 0.f;

    const uint32_t laneA = (uint32_t)((lane & 7) + ((lane >> 3) & 1) * 8) * ASTR
                         + ((lane >> 4) & 1) * 16;
    const uint32_t laneB = (uint32_t)((lane & 7) + ((lane >> 3) & 1) * 8) * BSTR
                         + ((lane >> 4) & 1) * 16;

    auto cpA = [&](int c, int buf) {
        int off = abase0 + c * CHK;
        bool valid = (off >= 0) && (off + 32 <= LL * EE);
        uint32_t sz = valid ? 16u : 0u;
        const char* src = (const char*)(Ab + (valid ? off : 0));
        uint32_t dst = sb + SM_STAGE + (uint32_t)buf * STAGE_SZ
                     + (uint32_t)rowA * ASTR + half * 64;
        cp16z(dst,      src,      sz);
        cp16z(dst + 16, src + 16, sz);
        cp16z(dst + 32, src + 32, sz);
        cp16z(dst + 48, src + 48, sz);
    };

    auto cpB = [&](int c, int buf) {
        const char* src = (const char*)(WB + (size_t)c * BCH);
        uint32_t dst = sb + SM_STAGE + (uint32_t)buf * STAGE_SZ + B_HI;
#pragma unroll
        for (int j = 0; j < 8; j++) {
            uint32_t u = tid + 256 * j;
            cp16(dst + u * 16, src + (size_t)u * 16);
        }
        uint32_t u = tid + 2048;
        if (u < 2112)
            cp16(dst + u * 16, src + (size_t)u * 16);
    };

    // single-pass MMA, 4 k16 slices per chunk
    auto do_mma = [&](uint32_t stg) {
#pragma unroll
        for (int kb = 0; kb < 4; kb++) {
            uint32_t af[4][4], bh[8][2];
#pragma unroll
            for (int mf = 0; mf < 4; mf++)
                ldsm4(af[mf], stg + A_HI +
                      (uint32_t)(wm * 64 + mf * 16) * ASTR + kb * 32 + laneA);
#pragma unroll
            for (int t = 0; t < 4; t++) {
                uint32_t r[4];
                ldsm4t(r, stg + B_HI + (uint32_t)kb * 16 * BSTR +
                       (uint32_t)(wn * 64 + t * 16) * 2 + laneB);
                bh[2 * t][0] = r[0]; bh[2 * t][1] = r[1];
                bh[2 * t + 1][0] = r[2]; bh[2 * t + 1][1] = r[3];
            }
#pragma unroll
            for (int mf = 0; mf < 4; mf++)
#pragma unroll
                for (int nf = 0; nf < 8; nf++)
                    mma_f16(d[mf][nf], af[mf], bh[nf]);
        }
    };

    // prologue: 3 chunks in flight
#pragma unroll
    for (int s = 0; s < 3; s++) {
        cpA(s, s); cpB(s, s);
        asm volatile("cp.async.commit_group;" ::: "memory");
    }

    for (int c = 0; c < NCH; c++) {
        if (c <= NCH - 3)
            asm volatile("cp.async.wait_group 2;" ::: "memory");
        else if (c == NCH - 2)
            asm volatile("cp.async.wait_group 1;" ::: "memory");
        else
            asm volatile("cp.async.wait_group 0;" ::: "memory");
        __syncthreads();
        if (c + 3 < NCH) {
            cpA(c + 3, (c + 3) & 3);
            cpB(c + 3, (c + 3) & 3);
            asm volatile("cp.async.commit_group;" ::: "memory");
        }
        do_mma(sb + SM_STAGE + (uint32_t)(c & 3) * STAGE_SZ);
    }

    // ------- epilogue: acc(+bias) -> smem tile -> per-row LN -------
    __syncthreads();
    float* tile_f = (float*)(smem + SM_STAGE);
#pragma unroll
    for (int mf = 0; mf < 4; mf++) {
        int r0 = wm * 64 + mf * 16 + (lane >> 2);
#pragma unroll
        for (int nf = 0; nf < 8; nf++) {
            int cc = wn * 64 + nf * 8 + (lane & 3) * 2;
            float b0 = smf[cc], b1v = smf[cc + 1];
            *reinterpret_cast<float2*>(tile_f + r0 * EPI_STRIDE + cc) =
                make_float2(d[mf][nf][0] + b0, d[mf][nf][1] + b1v);
            *reinterpret_cast<float2*>(tile_f + (r0 + 8) * EPI_STRIDE + cc) =
                make_float2(d[mf][nf][2] + b0, d[mf][nf][3] + b1v);
        }
    }
    __syncthreads();

    {
        int r = tid >> 1, h2 = tid & 1;
        const float4* row =
            (const float4*)(tile_f + r * EPI_STRIDE + h2 * 128);
        float sum = 0.f, ss = 0.f;
#pragma unroll
        for (int i = 0; i < 32; i++) {
            float4 v = row[i];
            sum += v.x + v.y + v.z + v.w;
            ss = fmaf(v.x, v.x, ss); ss = fmaf(v.y, v.y, ss);
            ss = fmaf(v.z, v.z, ss); ss = fmaf(v.w, v.w, ss);
        }
        sum += __shfl_xor_sync(0xffffffffu, sum, 1);
        ss  += __shfl_xor_sync(0xffffffffu, ss, 1);
        float mu  = sum * (1.f / 256.f);
        float inv = rsqrtf(ss * (1.f / 256.f) - mu * mu + 1e-5f);
        const float4* sG  = (const float4*)(smf + 256 + h2 * 128);
        const float4* sBe = (const float4*)(smf + 512 + h2 * 128);

        if (!isC2) {
            // store LN+relu output directly as fp16 (A operand of conv2)
            uint4* op = reinterpret_cast<uint4*>(
                g_H1h + (size_t)(m0 + r) * HH + h2 * 128);
#pragma unroll
            for (int i2 = 0; i2 < 16; i2++) {
                float4 v0 = row[2 * i2], v1 = row[2 * i2 + 1];
                float4 g0 = sG[2 * i2], g1v = sG[2 * i2 + 1];
                float4 b0 = sBe[2 * i2], b1v = sBe[2 * i2 + 1];
                float y0 = fmaxf(fmaf((v0.x - mu) * inv, g0.x, b0.x), 0.f);
                float y1 = fmaxf(fmaf((v0.y - mu) * inv, g0.y, b0.y), 0.f);
                float y2 = fmaxf(fmaf((v0.z - mu) * inv, g0.z, b0.z), 0.f);
                float y3 = fmaxf(fmaf((v0.w - mu) * inv, g0.w, b0.w), 0.f);
                float y4 = fmaxf(fmaf((v1.x - mu) * inv, g1v.x, b1v.x), 0.f);
                float y5 = fmaxf(fmaf((v1.y - mu) * inv, g1v.y, b1v.y), 0.f);
                float y6 = fmaxf(fmaf((v1.z - mu) * inv, g1v.z, b1v.z), 0.f);
                float y7 = fmaxf(fmaf((v1.w - mu) * inv, g1v.w, b1v.w), 0.f);
                uint4 p;
                p.x = pack_h2(y0, y1); p.y = pack_h2(y2, y3);
                p.z = pack_h2(y4, y5); p.w = pack_h2(y6, y7);
                op[i2] = p;
            }
        } else {
            const float4* sLw = (const float4*)(smf + 768 + h2 * 128);
            float dot = 0.f;
#pragma unroll
            for (int i = 0; i < 32; i++) {
                float4 v = row[i], g = sG[i], be = sBe[i], w = sLw[i];
                dot = fmaf(fmaxf(fmaf((v.x - mu) * inv, g.x, be.x), 0.f), w.x, dot);
                dot = fmaf(fmaxf(fmaf((v.y - mu) * inv, g.y, be.y), 0.f), w.y, dot);
                dot = fmaf(fmaxf(fmaf((v.z - mu) * inv, g.z, be.z), 0.f), w.z, dot);
                dot = fmaf(fmaxf(fmaf((v.w - mu) * inv, g.w, be.w), 0.f), w.w, dot);
            }
            dot += __shfl_xor_sync(0xffffffffu, dot, 1);
            if (h2 == 0) outDur[m0 + r] = fmaxf(dot + lb[0], 0.f);
        }
    }

    // conv1: publish tile completion
    if (!isC2) {
        __syncthreads();
        if (tid == 0) {
            __threadfence();
            atomicExch(&g_flag[tile], 1);
        }
    }
}

// ---------------------------------------------------------------------------
// Per-batch cumsum of target + searchsorted(right) -> g_idx[b,t] (-1 = zero)
// ---------------------------------------------------------------------------
__global__ void scan_idx(const int* __restrict__ target) {
    __shared__ int cum[LL];
    __shared__ int ps[256];
    int b = blockIdx.x;
    int tid = threadIdx.x;
    const int* tb = target + b * LL;
    int v[4], s = 0;
#pragma unroll
    for (int i = 0; i < 4; i++) { v[i] = tb[tid * 4 + i]; s += v[i]; }
    ps[tid] = s;
    __syncthreads();
    for (int o = 1; o < 256; o <<= 1) {
        int t = (tid >= o) ? ps[tid - o] : 0;
        __syncthreads();
        ps[tid] += t;
        __syncthreads();
    }
    int run = ps[tid] - s;
#pragma unroll
    for (int i = 0; i < 4; i++) { run += v[i]; cum[tid * 4 + i] = run; }
    __syncthreads();
    int total = cum[LL - 1];
    for (int t = tid; t < TT; t += 256) {
        int r = -1;
        if (t < total) {
            int lo = 0, hi = LL;
            while (lo < hi) {
                int mid = (lo + hi) >> 1;
                if (cum[mid] <= t) lo = mid + 1; else hi = mid;
            }
            r = lo < (LL - 1) ? lo : (LL - 1);
        }
        g_idx[b * TT + t] = r;
    }
}

// ---------------------------------------------------------------------------
// Gather/zero-fill: out[b,t,:] = (idx>=0) ? x[b,idx,:] : 0
// ---------------------------------------------------------------------------
__global__ void copy_out(const float* __restrict__ X, float* __restrict__ out) {
    int tid  = threadIdx.x;
    int rt   = blockIdx.x * 4 + (tid >> 6);
    int lane = tid & 63;
    int b = rt >> 13;
    int j = g_idx[rt];
    float4 val = make_float4(0.f, 0.f, 0.f, 0.f);
    if (j >= 0)
        val = *reinterpret_cast<const float4*>(X + (b * LL + j) * EE + lane * 4);
    *reinterpret_cast<float4*>(out + (size_t)rt * EE + lane * 4) = val;
}

// ---------------------------------------------------------------------------
extern "C" void kernel_launch(void* const* d_in, const int* in_sizes, int n_in,
                              void* d_out, int out_size) {
    const float* x      = (const float*)d_in[0];
    const int*   target = (const int*)  d_in[1];
    const float* c1w = (const float*)d_in[3];
    const float* c1b = (const float*)d_in[4];
    const float* g1  = (const float*)d_in[5];
    const float* b1  = (const float*)d_in[6];
    const float* c2w = (const float*)d_in[7];
    const float* c2b = (const float*)d_in[8];
    const float* g2  = (const float*)d_in[9];
    const float* b2  = (const float*)d_in[10];
    const float* lw  = (const float*)d_in[11];
    const float* lb  = (const float*)d_in[12];

    float* out = (float*)d_out;
    float* dur = out + OUT_OFF;

    __half *B1, *B2;
    cudaGetSymbolAddress((void**)&B1, g_B1);
    cudaGetSymbolAddress((void**)&B2, g_B2);

    cudaFuncSetAttribute(conv_fused, cudaFuncAttributeMaxDynamicSharedMemorySize,
                         SMEM_BYTES);

    // Streams + events for fork/join inside graph capture.
    static cudaStream_t s_side = nullptr, s_pre = nullptr;
    static cudaEvent_t  ev_fork = nullptr, ev_px = nullptr,
                        ev_pw2 = nullptr, ev_join = nullptr;
    if (s_side == nullptr) {
        cudaStreamCreateWithFlags(&s_side, cudaStreamNonBlocking);
        cudaStreamCreateWithFlags(&s_pre,  cudaStreamNonBlocking);
        cudaEventCreateWithFlags(&ev_fork, cudaEventDisableTiming);
        cudaEventCreateWithFlags(&ev_px,   cudaEventDisableTiming);
        cudaEventCreateWithFlags(&ev_pw2,  cudaEventDisableTiming);
        cudaEventCreateWithFlags(&ev_join, cudaEventDisableTiming);
    }

    cudaEventRecord(ev_fork, 0);
    cudaStreamWaitEvent(s_side, ev_fork, 0);
    cudaStreamWaitEvent(s_pre,  ev_fork, 0);

    // s_pre: prep_x (gates conv1 A reads)
    prep_x<<<MM * EE / 4 / 256, 256, 0, s_pre>>>(x);
    cudaEventRecord(ev_px, s_pre);

    // s_side: prep B2 first (gates conv2), then regulate path
    prep_w<<<(HH * KD + 255) / 256, 256, 0, s_side>>>(c2w, B2, 0);
    cudaEventRecord(ev_pw2, s_side);
    scan_idx<<<BB, 256, 0, s_side>>>(target);
    copy_out<<<(BB * TT) / 4, 256, 0, s_side>>>(x, out);
    cudaEventRecord(ev_join, s_side);

    // main: prep B1 (+flag reset folded in), then fused convs
    prep_w<<<(HH * KD + 255) / 256, 256>>>(c1w, B1, 1);
    cudaStreamWaitEvent(0, ev_px, 0);
    cudaStreamWaitEvent(0, ev_pw2, 0);
    conv_fused<<<2 * NTILES, 256, SMEM_BYTES>>>(c1b, g1, b1, c2b, g2, b2,
                                                lw, lb, dur);

    // join
    cudaStreamWaitEvent(0, ev_join, 0);
}

// round 16
// speedup vs baseline: 1.1133x; 1.0095x over previous
#include <cuda_runtime.h>
#include <cuda_fp16.h>
#include <cstdint>

// Problem constants
#define BB 32
#define LL 1024
#define EE 256
#define HH 256
#define TT 8192
#define KD 768                  // 3*256 im2col contraction
#define MM (BB*LL)              // 32768 rows
#define OUT_OFF (BB*TT*EE)      // duration follows output
#define NCH 12                  // K chunks of 64
#define CHK 64
#define NTILES (MM/128)         // 256 M-tiles per conv

// Weight blocks: per conv [NCH][64 k][264 n] fp16 (264 = 256 + pad)
#define BROW 264
#define BCH  (CHK*BROW)         // 16896 elems / chunk

__device__ __align__(16) __half g_Xh[MM*EE];    // fp16(x)
__device__ __align__(16) __half g_H1h[MM*HH];   // fp16 LN1 output
__device__ __align__(16) __half g_B1[NCH*BCH];
__device__ __align__(16) __half g_B2[NCH*BCH];
__device__ int g_flag[NTILES];                  // conv1 tile completion flags
__device__ int g_idx[BB*TT];

// SMEM layout (dynamic): params [0,4096), 4 stages from 4096; epilogue reuses stages
#define SM_STAGE 4096
#define A_HI 0
#define B_HI 18432              // A: 128 rows x 144B
#define STAGE_SZ 52224          // A 18432 + B 33792
#define ASTR 144                // A row stride bytes (64 fp16 + 16 pad)
#define BSTR 528                // B row stride bytes (264 fp16)
#define EPI_STRIDE 264          // epilogue fp32 tile row stride (floats)
#define SMEM_BYTES (4096 + 4*STAGE_SZ)   // 212992 (> epilogue 139264; < 227KB)

__device__ __forceinline__ void ldsm4(uint32_t* r, uint32_t a) {
    asm volatile("ldmatrix.sync.aligned.m8n8.x4.shared.b16 {%0,%1,%2,%3}, [%4];"
        : "=r"(r[0]), "=r"(r[1]), "=r"(r[2]), "=r"(r[3]) : "r"(a));
}
__device__ __forceinline__ void ldsm4t(uint32_t* r, uint32_t a) {
    asm volatile("ldmatrix.sync.aligned.m8n8.x4.trans.shared.b16 {%0,%1,%2,%3}, [%4];"
        : "=r"(r[0]), "=r"(r[1]), "=r"(r[2]), "=r"(r[3]) : "r"(a));
}
__device__ __forceinline__ void mma_f16(float* d, const uint32_t* a, const uint32_t* b) {
    asm volatile(
        "mma.sync.aligned.m16n8k16.row.col.f32.f16.f16.f32 "
        "{%0,%1,%2,%3}, {%4,%5,%6,%7}, {%8,%9}, {%0,%1,%2,%3};"
        : "+f"(d[0]), "+f"(d[1]), "+f"(d[2]), "+f"(d[3])
        : "r"(a[0]), "r"(a[1]), "r"(a[2]), "r"(a[3]), "r"(b[0]), "r"(b[1]));
}
__device__ __forceinline__ uint32_t pack_h2(float x, float y) {
    __half2 h = __floats2half2_rn(x, y);
    return *reinterpret_cast<uint32_t*>(&h);
}
__device__ __forceinline__ void cp16(uint32_t dst, const void* src) {
    asm volatile("cp.async.cg.shared.global [%0], [%1], 16;"
        :: "r"(dst), "l"(src) : "memory");
}
// zero-fill variant: src-size 0 -> smem gets zeros
__device__ __forceinline__ void cp16z(uint32_t dst, const void* src, uint32_t sz) {
    asm volatile("cp.async.cg.shared.global [%0], [%1], 16, %2;"
        :: "r"(dst), "l"(src), "r"(sz) : "memory");
}

// ---------------------------------------------------------------------------
// X fp32 -> fp16 plane
__global__ void prep_x(const float* __restrict__ X) {
    int i = blockIdx.x * blockDim.x + threadIdx.x;   // one float4 per thread
    float4 v = reinterpret_cast<const float4*>(X)[i];
    uint2 hh;
    hh.x = pack_h2(v.x, v.y);
    hh.y = pack_h2(v.z, v.w);
    reinterpret_cast<uint2*>(g_Xh)[i] = hh;
}

// Weight prep (one conv): [H,E,K] fp32 -> fp16 in [chunk][k'][n=h].
// zero_flags!=0: block 0 also resets the conv1 completion flags.
__global__ void prep_w(const float* __restrict__ w, __half* __restrict__ dst,
                       int zero_flags) {
    int i = blockIdx.x * blockDim.x + threadIdx.x;
    if (zero_flags && blockIdx.x == 0 && threadIdx.x < NTILES)
        g_flag[threadIdx.x] = 0;
    if (i >= HH * KD) return;
    int h = i / KD, kk = i % KD;
    int k = kk / EE, e = kk % EE;
    int c = kk >> 6, kp = kk & 63;
    dst[((size_t)c * CHK + kp) * BROW + h] = __float2half_rn(w[(h * EE + e) * 3 + k]);
}

// ---------------------------------------------------------------------------
// Fused conv1+conv2 via inter-block flags.
// blocks [0,256): conv1 tile = bid   -> H1h fp16, signal g_flag[tile]
// blocks [256,512): conv2 tile = bid-256, waits flags t-1,t,t+1 (batch-clamped)
//                  -> duration
// 256 threads: warp grid 2(M) x 4(N), warp tile 64x64. 12 K-chunks of 64.
// 4-stage cp.async pipeline + register double-buffered fragments.
// ---------------------------------------------------------------------------
__global__ void __launch_bounds__(256, 1)
conv_fused(const float* __restrict__ c1b, const float* __restrict__ g1,
           const float* __restrict__ b1, const float* __restrict__ c2b,
           const float* __restrict__ g2, const float* __restrict__ b2,
           const float* __restrict__ lw, const float* __restrict__ lb,
           float* __restrict__ outDur)
{
    extern __shared__ char smem[];
    const int tid = threadIdx.x, lane = tid & 31, wid = tid >> 5;
    const int wm = wid >> 2, wn = wid & 3;       // 2 (M) x 4 (N) warps
    const bool isC2 = blockIdx.x >= NTILES;
    const int tile = blockIdx.x & (NTILES - 1);
    uint32_t sb;
    asm("{ .reg .u64 t; cvta.to.shared.u64 t, %1; cvt.u32.u64 %0, t; }"
        : "=r"(sb) : "l"(smem));

    const __half* Ain = isC2 ? g_H1h : g_Xh;
    const __half* WB  = isC2 ? g_B2  : g_B1;
    const float* bias = isC2 ? c2b : c1b;
    const float* gam  = isC2 ? g2  : g1;
    const float* bet  = isC2 ? b2  : b1;

    // params into smem: bias @0, gamma @256, beta @512, lw @768 (floats)
    float* smf = (float*)smem;
    smf[tid]       = bias[tid];
    smf[256 + tid] = gam[tid];
    smf[512 + tid] = bet[tid];
    smf[768 + tid] = lw[tid];

    // conv2: wait for producer tiles (t-1, t, t+1 within this tile's batch),
    // 3 threads poll in parallel.
    if (isC2) {
        if (tid < 3) {
            int lo = (tile & 7) ? tile - 1 : tile;          // 8 tiles per batch
            int hi = ((tile & 7) == 7) ? tile : tile + 1;
            int t = (tid == 0) ? lo : ((tid == 1) ? tile : hi);
            while (atomicAdd(&g_flag[t], 0) == 0) __nanosleep(64);
            __threadfence();
        }
        __syncthreads();
    }

    const int m0 = tile * 128;
    const __half* Ab = Ain + (size_t)(m0 >> 10) * (LL * EE);
    const int rowA = tid >> 1, half = tid & 1;
    const int lg = (m0 & (LL - 1)) + rowA;
    const int abase0 = (lg - 1) * EE + half * 32;   // elems; 32 elems per thread

    float d[4][8][4];
#pragma unroll
    for (int i = 0; i < 4; i++)
#pragma unroll
        for (int j = 0; j < 8; j++)
#pragma unroll
            for (int q = 0; q < 4; q++) d[i][j][q] = 0.f;

    const uint32_t laneA = (uint32_t)((lane & 7) + ((lane >> 3) & 1) * 8) * ASTR
                         + ((lane >> 4) & 1) * 16;
    const uint32_t laneB = (uint32_t)((lane & 7) + ((lane >> 3) & 1) * 8) * BSTR
                         + ((lane >> 4) & 1) * 16;

    auto cpA = [&](int c, int buf) {
        int off = abase0 + c * CHK;
        bool valid = (off >= 0) && (off + 32 <= LL * EE);
        uint32_t sz = valid ? 16u : 0u;
        const char* src = (const char*)(Ab + (valid ? off : 0));
        uint32_t dst = sb + SM_STAGE + (uint32_t)buf * STAGE_SZ
                     + (uint32_t)rowA * ASTR + half * 64;
        cp16z(dst,      src,      sz);
        cp16z(dst + 16, src + 16, sz);
        cp16z(dst + 32, src + 32, sz);
        cp16z(dst + 48, src + 48, sz);
    };

    auto cpB = [&](int c, int buf) {
        const char* src = (const char*)(WB + (size_t)c * BCH);
        uint32_t dst = sb + SM_STAGE + (uint32_t)buf * STAGE_SZ + B_HI;
#pragma unroll
        for (int j = 0; j < 8; j++) {
            uint32_t u = tid + 256 * j;
            cp16(dst + u * 16, src + (size_t)u * 16);
        }
        uint32_t u = tid + 2048;
        if (u < 2112)
            cp16(dst + u * 16, src + (size_t)u * 16);
    };

    // fragment loaders (one k16 slice)
    auto ldA = [&](uint32_t stg, int kb, uint32_t af[4][4]) {
#pragma unroll
        for (int mf = 0; mf < 4; mf++)
            ldsm4(af[mf], stg + A_HI +
                  (uint32_t)(wm * 64 + mf * 16) * ASTR + kb * 32 + laneA);
    };
    auto ldB = [&](uint32_t stg, int kb, uint32_t bh[8][2]) {
#pragma unroll
        for (int t = 0; t < 4; t++) {
            uint32_t r[4];
            ldsm4t(r, stg + B_HI + (uint32_t)kb * 16 * BSTR +
                   (uint32_t)(wn * 64 + t * 16) * 2 + laneB);
            bh[2 * t][0] = r[0]; bh[2 * t][1] = r[1];
            bh[2 * t + 1][0] = r[2]; bh[2 * t + 1][1] = r[3];
        }
    };
    auto mmaSlice = [&](uint32_t af[4][4], uint32_t bh[8][2]) {
#pragma unroll
        for (int mf = 0; mf < 4; mf++)
#pragma unroll
            for (int nf = 0; nf < 8; nf++)
                mma_f16(d[mf][nf], af[mf], bh[nf]);
    };

    // double-buffered do_mma: prefetch slice kb+1 fragments under slice kb MMAs
    auto do_mma = [&](uint32_t stg) {
        uint32_t afA[4][4], bhA[8][2], afB[4][4], bhB[8][2];
        ldA(stg, 0, afA); ldB(stg, 0, bhA);
#pragma unroll
        for (int kb = 0; kb < 4; kb++) {
            if (kb & 1) {
                if (kb < 3) { ldA(stg, kb + 1, afA); ldB(stg, kb + 1, bhA); }
                mmaSlice(afB, bhB);
            } else {
                if (kb < 3) { ldA(stg, kb + 1, afB); ldB(stg, kb + 1, bhB); }
                mmaSlice(afA, bhA);
            }
        }
    };

    // prologue: 3 chunks in flight
#pragma unroll
    for (int s = 0; s < 3; s++) {
        cpA(s, s); cpB(s, s);
        asm volatile("cp.async.commit_group;" ::: "memory");
    }

    for (int c = 0; c < NCH; c++) {
        if (c <= NCH - 3)
            asm volatile("cp.async.wait_group 2;" ::: "memory");
        else if (c == NCH - 2)
            asm volatile("cp.async.wait_group 1;" ::: "memory");
        else
            asm volatile("cp.async.wait_group 0;" ::: "memory");
        __syncthreads();
        if (c + 3 < NCH) {
            cpA(c + 3, (c + 3) & 3);
            cpB(c + 3, (c + 3) & 3);
            asm volatile("cp.async.commit_group;" ::: "memory");
        }
        do_mma(sb + SM_STAGE + (uint32_t)(c & 3) * STAGE_SZ);
    }

    // ------- epilogue: acc(+bias) -> smem tile -> per-row LN -------
    __syncthreads();
    float* tile_f = (float*)(smem + SM_STAGE);
#pragma unroll
    for (int mf = 0; mf < 4; mf++) {
        int r0 = wm * 64 + mf * 16 + (lane >> 2);
#pragma unroll
        for (int nf = 0; nf < 8; nf++) {
            int cc = wn * 64 + nf * 8 + (lane & 3) * 2;
            float b0 = smf[cc], b1v = smf[cc + 1];
            *reinterpret_cast<float2*>(tile_f + r0 * EPI_STRIDE + cc) =
                make_float2(d[mf][nf][0] + b0, d[mf][nf][1] + b1v);
            *reinterpret_cast<float2*>(tile_f + (r0 + 8) * EPI_STRIDE + cc) =
                make_float2(d[mf][nf][2] + b0, d[mf][nf][3] + b1v);
        }
    }
    __syncthreads();

    {
        int r = tid >> 1, h2 = tid & 1;
        const float4* row =
            (const float4*)(tile_f + r * EPI_STRIDE + h2 * 128);
        float sum = 0.f, ss = 0.f;
#pragma unroll
        for (int i = 0; i < 32; i++) {
            float4 v = row[i];
            sum += v.x + v.y + v.z + v.w;
            ss = fmaf(v.x, v.x, ss); ss = fmaf(v.y, v.y, ss);
            ss = fmaf(v.z, v.z, ss); ss = fmaf(v.w, v.w, ss);
        }
        sum += __shfl_xor_sync(0xffffffffu, sum, 1);
        ss  += __shfl_xor_sync(0xffffffffu, ss, 1);
        float mu  = sum * (1.f / 256.f);
        float inv = rsqrtf(ss * (1.f / 256.f) - mu * mu + 1e-5f);
        const float4* sG  = (const float4*)(smf + 256 + h2 * 128);
        const float4* sBe = (const float4*)(smf + 512 + h2 * 128);

        if (!isC2) {
            // store LN+relu output directly as fp16 (A operand of conv2)
            uint4* op = reinterpret_cast<uint4*>(
                g_H1h + (size_t)(m0 + r) * HH + h2 * 128);
#pragma unroll
            for (int i2 = 0; i2 < 16; i2++) {
                float4 v0 = row[2 * i2], v1 = row[2 * i2 + 1];
                float4 g0 = sG[2 * i2], g1v = sG[2 * i2 + 1];
                float4 b0 = sBe[2 * i2], b1v = sBe[2 * i2 + 1];
                float y0 = fmaxf(fmaf((v0.x - mu) * inv, g0.x, b0.x), 0.f);
                float y1 = fmaxf(fmaf((v0.y - mu) * inv, g0.y, b0.y), 0.f);
                float y2 = fmaxf(fmaf((v0.z - mu) * inv, g0.z, b0.z), 0.f);
                float y3 = fmaxf(fmaf((v0.w - mu) * inv, g0.w, b0.w), 0.f);
                float y4 = fmaxf(fmaf((v1.x - mu) * inv, g1v.x, b1v.x), 0.f);
                float y5 = fmaxf(fmaf((v1.y - mu) * inv, g1v.y, b1v.y), 0.f);
                float y6 = fmaxf(fmaf((v1.z - mu) * inv, g1v.z, b1v.z), 0.f);
                float y7 = fmaxf(fmaf((v1.w - mu) * inv, g1v.w, b1v.w), 0.f);
                uint4 p;
                p.x = pack_h2(y0, y1); p.y = pack_h2(y2, y3);
                p.z = pack_h2(y4, y5); p.w = pack_h2(y6, y7);
                op[i2] = p;
            }
        } else {
            const float4* sLw = (const float4*)(smf + 768 + h2 * 128);
            float dot = 0.f;
#pragma unroll
            for (int i = 0; i < 32; i++) {
                float4 v = row[i], g = sG[i], be = sBe[i], w = sLw[i];
                dot = fmaf(fmaxf(fmaf((v.x - mu) * inv, g.x, be.x), 0.f), w.x, dot);
                dot = fmaf(fmaxf(fmaf((v.y - mu) * inv, g.y, be.y), 0.f), w.y, dot);
                dot = fmaf(fmaxf(fmaf((v.z - mu) * inv, g.z, be.z), 0.f), w.z, dot);
                dot = fmaf(fmaxf(fmaf((v.w - mu) * inv, g.w, be.w), 0.f), w.w, dot);
            }
            dot += __shfl_xor_sync(0xffffffffu, dot, 1);
            if (h2 == 0) outDur[m0 + r] = fmaxf(dot + lb[0], 0.f);
        }
    }

    // conv1: publish tile completion
    if (!isC2) {
        __syncthreads();
        if (tid == 0) {
            __threadfence();
            atomicExch(&g_flag[tile], 1);
        }
    }
}

// ---------------------------------------------------------------------------
// Per-batch cumsum of target + searchsorted(right) -> g_idx[b,t] (-1 = zero)
// ---------------------------------------------------------------------------
__global__ void scan_idx(const int* __restrict__ target) {
    __shared__ int cum[LL];
    __shared__ int ps[256];
    int b = blockIdx.x;
    int tid = threadIdx.x;
    const int* tb = target + b * LL;
    int v[4], s = 0;
#pragma unroll
    for (int i = 0; i < 4; i++) { v[i] = tb[tid * 4 + i]; s += v[i]; }
    ps[tid] = s;
    __syncthreads();
    for (int o = 1; o < 256; o <<= 1) {
        int t = (tid >= o) ? ps[tid - o] : 0;
        __syncthreads();
        ps[tid] += t;
        __syncthreads();
    }
    int run = ps[tid] - s;
#pragma unroll
    for (int i = 0; i < 4; i++) { run += v[i]; cum[tid * 4 + i] = run; }
    __syncthreads();
    int total = cum[LL - 1];
    for (int t = tid; t < TT; t += 256) {
        int r = -1;
        if (t < total) {
            int lo = 0, hi = LL;
            while (lo < hi) {
                int mid = (lo + hi) >> 1;
                if (cum[mid] <= t) lo = mid + 1; else hi = mid;
            }
            r = lo < (LL - 1) ? lo : (LL - 1);
        }
        g_idx[b * TT + t] = r;
    }
}

// ---------------------------------------------------------------------------
// Gather/zero-fill: out[b,t,:] = (idx>=0) ? x[b,idx,:] : 0
// ---------------------------------------------------------------------------
__global__ void copy_out(const float* __restrict__ X, float* __restrict__ out) {
    int tid  = threadIdx.x;
    int rt   = blockIdx.x * 4 + (tid >> 6);
    int lane = tid & 63;
    int b = rt >> 13;
    int j = g_idx[rt];
    float4 val = make_float4(0.f, 0.f, 0.f, 0.f);
    if (j >= 0)
        val = *reinterpret_cast<const float4*>(X + (b * LL + j) * EE + lane * 4);
    *reinterpret_cast<float4*>(out + (size_t)rt * EE + lane * 4) = val;
}

// ---------------------------------------------------------------------------
extern "C" void kernel_launch(void* const* d_in, const int* in_sizes, int n_in,
                              void* d_out, int out_size) {
    const float* x      = (const float*)d_in[0];
    const int*   target = (const int*)  d_in[1];
    const float* c1w = (const float*)d_in[3];
    const float* c1b = (const float*)d_in[4];
    const float* g1  = (const float*)d_in[5];
    const float* b1  = (const float*)d_in[6];
    const float* c2w = (const float*)d_in[7];
    const float* c2b = (const float*)d_in[8];
    const float* g2  = (const float*)d_in[9];
    const float* b2  = (const float*)d_in[10];
    const float* lw  = (const float*)d_in[11];
    const float* lb  = (const float*)d_in[12];

    float* out = (float*)d_out;
    float* dur = out + OUT_OFF;

    __half *B1, *B2;
    cudaGetSymbolAddress((void**)&B1, g_B1);
    cudaGetSymbolAddress((void**)&B2, g_B2);

    cudaFuncSetAttribute(conv_fused, cudaFuncAttributeMaxDynamicSharedMemorySize,
                         SMEM_BYTES);

    // Streams + events for fork/join inside graph capture.
    static cudaStream_t s_side = nullptr, s_pre = nullptr;
    static cudaEvent_t  ev_fork = nullptr, ev_px = nullptr,
                        ev_pw2 = nullptr, ev_join = nullptr;
    if (s_side == nullptr) {
        cudaStreamCreateWithFlags(&s_side, cudaStreamNonBlocking);
        cudaStreamCreateWithFlags(&s_pre,  cudaStreamNonBlocking);
        cudaEventCreateWithFlags(&ev_fork, cudaEventDisableTiming);
        cudaEventCreateWithFlags(&ev_px,   cudaEventDisableTiming);
        cudaEventCreateWithFlags(&ev_pw2,  cudaEventDisableTiming);
        cudaEventCreateWithFlags(&ev_join, cudaEventDisableTiming);
    }

    cudaEventRecord(ev_fork, 0);
    cudaStreamWaitEvent(s_side, ev_fork, 0);
    cudaStreamWaitEvent(s_pre,  ev_fork, 0);

    // s_pre: prep_x (gates conv1 A reads)
    prep_x<<<MM * EE / 4 / 256, 256, 0, s_pre>>>(x);
    cudaEventRecord(ev_px, s_pre);

    // s_side: prep B2 first (gates conv2), then regulate path
    prep_w<<<(HH * KD + 255) / 256, 256, 0, s_side>>>(c2w, B2, 0);
    cudaEventRecord(ev_pw2, s_side);
    scan_idx<<<BB, 256, 0, s_side>>>(target);
    copy_out<<<(BB * TT) / 4, 256, 0, s_side>>>(x, out);
    cudaEventRecord(ev_join, s_side);

    // main: prep B1 (+flag reset folded in), then fused convs
    prep_w<<<(HH * KD + 255) / 256, 256>>>(c1w, B1, 1);
    cudaStreamWaitEvent(0, ev_px, 0);
    cudaStreamWaitEvent(0, ev_pw2, 0);
    conv_fused<<<2 * NTILES, 256, SMEM_BYTES>>>(c1b, g1, b1, c2b, g2, b2,
                                                lw, lb, dur);

    // join
    cudaStreamWaitEvent(0, ev_join, 0);
}

// round 17
// speedup vs baseline: 1.2543x; 1.1267x over previous
#include <cuda_runtime.h>
#include <cuda_fp16.h>
#include <cstdint>

// Problem constants
#define BB 32
#define LL 1024
#define EE 256
#define HH 256
#define TT 8192
#define KD 768                  // 3*256 im2col contraction
#define MM (BB*LL)              // 32768 rows
#define OUT_OFF (BB*TT*EE)      // duration follows output
#define NCH 12                  // K chunks of 64
#define CHK 64
#define NTILES (MM/128)         // 256 M-tiles per conv
#define CO_GRID 4096            // copy_out grid (grid-stride)

// Weight blocks: per conv [NCH][64 k][264 n] fp16 (264 = 256 + pad)
#define BROW 264
#define BCH  (CHK*BROW)         // 16896 elems / chunk

__device__ __align__(16) __half g_Xh[MM*EE];    // fp16(x)
__device__ __align__(16) __half g_H1h[MM*HH];   // fp16 LN1 output
__device__ __align__(16) __half g_B1[NCH*BCH];
__device__ __align__(16) __half g_B2[NCH*BCH];
__device__ int g_flag[NTILES];                  // conv1 tile completion flags
__device__ int g_idx[BB*TT];

// SMEM layout (dynamic): params [0,4096), 4 stages from 4096; epilogue reuses stages
#define SM_STAGE 4096
#define A_HI 0
#define B_HI 18432              // A: 128 rows x 144B
#define STAGE_SZ 52224          // A 18432 + B 33792
#define ASTR 144                // A row stride bytes (64 fp16 + 16 pad)
#define BSTR 528                // B row stride bytes (264 fp16)
#define EPI_STRIDE 264          // epilogue fp32 tile row stride (floats)
#define SMEM_BYTES (4096 + 4*STAGE_SZ)   // 212992 (> epilogue 139264; < 227KB)

__device__ __forceinline__ void ldsm4(uint32_t* r, uint32_t a) {
    asm volatile("ldmatrix.sync.aligned.m8n8.x4.shared.b16 {%0,%1,%2,%3}, [%4];"
        : "=r"(r[0]), "=r"(r[1]), "=r"(r[2]), "=r"(r[3]) : "r"(a));
}
__device__ __forceinline__ void ldsm4t(uint32_t* r, uint32_t a) {
    asm volatile("ldmatrix.sync.aligned.m8n8.x4.trans.shared.b16 {%0,%1,%2,%3}, [%4];"
        : "=r"(r[0]), "=r"(r[1]), "=r"(r[2]), "=r"(r[3]) : "r"(a));
}
__device__ __forceinline__ void mma_f16(float* d, const uint32_t* a, const uint32_t* b) {
    asm volatile(
        "mma.sync.aligned.m16n8k16.row.col.f32.f16.f16.f32 "
        "{%0,%1,%2,%3}, {%4,%5,%6,%7}, {%8,%9}, {%0,%1,%2,%3};"
        : "+f"(d[0]), "+f"(d[1]), "+f"(d[2]), "+f"(d[3])
        : "r"(a[0]), "r"(a[1]), "r"(a[2]), "r"(a[3]), "r"(b[0]), "r"(b[1]));
}
__device__ __forceinline__ uint32_t pack_h2(float x, float y) {
    __half2 h = __floats2half2_rn(x, y);
    return *reinterpret_cast<uint32_t*>(&h);
}
__device__ __forceinline__ void cp16(uint32_t dst, const void* src) {
    asm volatile("cp.async.cg.shared.global [%0], [%1], 16;"
        :: "r"(dst), "l"(src) : "memory");
}
// zero-fill variant: src-size 0 -> smem gets zeros
__device__ __forceinline__ void cp16z(uint32_t dst, const void* src, uint32_t sz) {
    asm volatile("cp.async.cg.shared.global [%0], [%1], 16, %2;"
        :: "r"(dst), "l"(src), "r"(sz) : "memory");
}

// ---------------------------------------------------------------------------
// X fp32 -> fp16 plane
__global__ void prep_x(const float* __restrict__ X) {
    int i = blockIdx.x * blockDim.x + threadIdx.x;   // one float4 per thread
    float4 v = reinterpret_cast<const float4*>(X)[i];
    uint2 hh;
    hh.x = pack_h2(v.x, v.y);
    hh.y = pack_h2(v.z, v.w);
    reinterpret_cast<uint2*>(g_Xh)[i] = hh;
}

// Weight prep (one conv): [H,E,K] fp32 -> fp16 in [chunk][k'][n=h].
// block = kk (im2col k index), thread = h  -> writes are 512B-contiguous.
// zero_flags!=0: block 0 also resets the conv1 completion flags.
__global__ void prep_w(const float* __restrict__ w, __half* __restrict__ dst,
                       int zero_flags) {
    int kk = blockIdx.x;         // [0, KD)
    int h  = threadIdx.x;        // [0, HH)
    if (zero_flags && kk == 0 && h < NTILES) g_flag[h] = 0;
    int k = kk / EE, e = kk % EE;
    int c = kk >> 6, kp = kk & 63;
    dst[((size_t)c * CHK + kp) * BROW + h] =
        __float2half_rn(w[(h * EE + e) * 3 + k]);
}

// ---------------------------------------------------------------------------
// Fused conv1+conv2 via inter-block flags.
// blocks [0,256): conv1 tile = bid   -> H1h fp16, signal g_flag[tile]
// blocks [256,512): conv2 tile = bid-256, waits flags t-1,t,t+1 (batch-clamped)
//                  -> duration
// 256 threads: warp grid 2(M) x 4(N), warp tile 64x64. 12 K-chunks of 64.
// 4-stage cp.async pipeline + register double-buffered fragments.
// ---------------------------------------------------------------------------
__global__ void __launch_bounds__(256, 1)
conv_fused(const float* __restrict__ c1b, const float* __restrict__ g1,
           const float* __restrict__ b1, const float* __restrict__ c2b,
           const float* __restrict__ g2, const float* __restrict__ b2,
           const float* __restrict__ lw, const float* __restrict__ lb,
           float* __restrict__ outDur)
{
    extern __shared__ char smem[];
    const int tid = threadIdx.x, lane = tid & 31, wid = tid >> 5;
    const int wm = wid >> 2, wn = wid & 3;       // 2 (M) x 4 (N) warps
    const bool isC2 = blockIdx.x >= NTILES;
    const int tile = blockIdx.x & (NTILES - 1);
    uint32_t sb;
    asm("{ .reg .u64 t; cvta.to.shared.u64 t, %1; cvt.u32.u64 %0, t; }"
        : "=r"(sb) : "l"(smem));

    const __half* Ain = isC2 ? g_H1h : g_Xh;
    const __half* WB  = isC2 ? g_B2  : g_B1;
    const float* bias = isC2 ? c2b : c1b;
    const float* gam  = isC2 ? g2  : g1;
    const float* bet  = isC2 ? b2  : b1;

    // params into smem: bias @0, gamma @256, beta @512, lw @768 (floats)
    float* smf = (float*)smem;
    smf[tid]       = bias[tid];
    smf[256 + tid] = gam[tid];
    smf[512 + tid] = bet[tid];
    smf[768 + tid] = lw[tid];

    // conv2: wait for producer tiles (t-1, t, t+1 within this tile's batch),
    // 3 threads poll in parallel.
    if (isC2) {
        if (tid < 3) {
            int lo = (tile & 7) ? tile - 1 : tile;          // 8 tiles per batch
            int hi = ((tile & 7) == 7) ? tile : tile + 1;
            int t = (tid == 0) ? lo : ((tid == 1) ? tile : hi);
            while (atomicAdd(&g_flag[t], 0) == 0) __nanosleep(64);
            __threadfence();
        }
        __syncthreads();
    }

    const int m0 = tile * 128;
    const __half* Ab = Ain + (size_t)(m0 >> 10) * (LL * EE);
    const int rowA = tid >> 1, half = tid & 1;
    const int lg = (m0 & (LL - 1)) + rowA;
    const int abase0 = (lg - 1) * EE + half * 32;   // elems; 32 elems per thread

    float d[4][8][4];
#pragma unroll
    for (int i = 0; i < 4; i++)
#pragma unroll
        for (int j = 0; j < 8; j++)
#pragma unroll
            for (int q = 0; q < 4; q++) d[i][j][q] = 0.f;

    const uint32_t laneA = (uint32_t)((lane & 7) + ((lane >> 3) & 1) * 8) * ASTR
                         + ((lane >> 4) & 1) * 16;
    const uint32_t laneB = (uint32_t)((lane & 7) + ((lane >> 3) & 1) * 8) * BSTR
                         + ((lane >> 4) & 1) * 16;

    auto cpA = [&](int c, int buf) {
        int off = abase0 + c * CHK;
        bool valid = (off >= 0) && (off + 32 <= LL * EE);
        uint32_t sz = valid ? 16u : 0u;
        const char* src = (const char*)(Ab + (valid ? off : 0));
        uint32_t dst = sb + SM_STAGE + (uint32_t)buf * STAGE_SZ
                     + (uint32_t)rowA * ASTR + half * 64;
        cp16z(dst,      src,      sz);
        cp16z(dst + 16, src + 16, sz);
        cp16z(dst + 32, src + 32, sz);
        cp16z(dst + 48, src + 48, sz);
    };

    auto cpB = [&](int c, int buf) {
        const char* src = (const char*)(WB + (size_t)c * BCH);
        uint32_t dst = sb + SM_STAGE + (uint32_t)buf * STAGE_SZ + B_HI;
#pragma unroll
        for (int j = 0; j < 8; j++) {
            uint32_t u = tid + 256 * j;
            cp16(dst + u * 16, src + (size_t)u * 16);
        }
        uint32_t u = tid + 2048;
        if (u < 2112)
            cp16(dst + u * 16, src + (size_t)u * 16);
    };

    // fragment loaders (one k16 slice)
    auto ldA = [&](uint32_t stg, int kb, uint32_t af[4][4]) {
#pragma unroll
        for (int mf = 0; mf < 4; mf++)
            ldsm4(af[mf], stg + A_HI +
                  (uint32_t)(wm * 64 + mf * 16) * ASTR + kb * 32 + laneA);
    };
    auto ldB = [&](uint32_t stg, int kb, uint32_t bh[8][2]) {
#pragma unroll
        for (int t = 0; t < 4; t++) {
            uint32_t r[4];
            ldsm4t(r, stg + B_HI + (uint32_t)kb * 16 * BSTR +
                   (uint32_t)(wn * 64 + t * 16) * 2 + laneB);
            bh[2 * t][0] = r[0]; bh[2 * t][1] = r[1];
            bh[2 * t + 1][0] = r[2]; bh[2 * t + 1][1] = r[3];
        }
    };
    auto mmaSlice = [&](uint32_t af[4][4], uint32_t bh[8][2]) {
#pragma unroll
        for (int mf = 0; mf < 4; mf++)
#pragma unroll
            for (int nf = 0; nf < 8; nf++)
                mma_f16(d[mf][nf], af[mf], bh[nf]);
    };

    // double-buffered do_mma: prefetch slice kb+1 fragments under slice kb MMAs
    auto do_mma = [&](uint32_t stg) {
        uint32_t afA[4][4], bhA[8][2], afB[4][4], bhB[8][2];
        ldA(stg, 0, afA); ldB(stg, 0, bhA);
#pragma unroll
        for (int kb = 0; kb < 4; kb++) {
            if (kb & 1) {
                if (kb < 3) { ldA(stg, kb + 1, afA); ldB(stg, kb + 1, bhA); }
                mmaSlice(afB, bhB);
            } else {
                if (kb < 3) { ldA(stg, kb + 1, afB); ldB(stg, kb + 1, bhB); }
                mmaSlice(afA, bhA);
            }
        }
    };

    // prologue: 3 chunks in flight
#pragma unroll
    for (int s = 0; s < 3; s++) {
        cpA(s, s); cpB(s, s);
        asm volatile("cp.async.commit_group;" ::: "memory");
    }

    for (int c = 0; c < NCH; c++) {
        if (c <= NCH - 3)
            asm volatile("cp.async.wait_group 2;" ::: "memory");
        else if (c == NCH - 2)
            asm volatile("cp.async.wait_group 1;" ::: "memory");
        else
            asm volatile("cp.async.wait_group 0;" ::: "memory");
        __syncthreads();
        if (c + 3 < NCH) {
            cpA(c + 3, (c + 3) & 3);
            cpB(c + 3, (c + 3) & 3);
            asm volatile("cp.async.commit_group;" ::: "memory");
        }
        do_mma(sb + SM_STAGE + (uint32_t)(c & 3) * STAGE_SZ);
    }

    // ------- epilogue: acc(+bias) -> smem tile -> per-row LN -------
    __syncthreads();
    float* tile_f = (float*)(smem + SM_STAGE);
#pragma unroll
    for (int mf = 0; mf < 4; mf++) {
        int r0 = wm * 64 + mf * 16 + (lane >> 2);
#pragma unroll
        for (int nf = 0; nf < 8; nf++) {
            int cc = wn * 64 + nf * 8 + (lane & 3) * 2;
            float b0 = smf[cc], b1v = smf[cc + 1];
            *reinterpret_cast<float2*>(tile_f + r0 * EPI_STRIDE + cc) =
                make_float2(d[mf][nf][0] + b0, d[mf][nf][1] + b1v);
            *reinterpret_cast<float2*>(tile_f + (r0 + 8) * EPI_STRIDE + cc) =
                make_float2(d[mf][nf][2] + b0, d[mf][nf][3] + b1v);
        }
    }
    __syncthreads();

    {
        int r = tid >> 1, h2 = tid & 1;
        const float4* row =
            (const float4*)(tile_f + r * EPI_STRIDE + h2 * 128);
        float sum = 0.f, ss = 0.f;
#pragma unroll
        for (int i = 0; i < 32; i++) {
            float4 v = row[i];
            sum += v.x + v.y + v.z + v.w;
            ss = fmaf(v.x, v.x, ss); ss = fmaf(v.y, v.y, ss);
            ss = fmaf(v.z, v.z, ss); ss = fmaf(v.w, v.w, ss);
        }
        sum += __shfl_xor_sync(0xffffffffu, sum, 1);
        ss  += __shfl_xor_sync(0xffffffffu, ss, 1);
        float mu  = sum * (1.f / 256.f);
        float inv = rsqrtf(ss * (1.f / 256.f) - mu * mu + 1e-5f);
        const float4* sG  = (const float4*)(smf + 256 + h2 * 128);
        const float4* sBe = (const float4*)(smf + 512 + h2 * 128);

        if (!isC2) {
            // store LN+relu output directly as fp16 (A operand of conv2)
            uint4* op = reinterpret_cast<uint4*>(
                g_H1h + (size_t)(m0 + r) * HH + h2 * 128);
#pragma unroll
            for (int i2 = 0; i2 < 16; i2++) {
                float4 v0 = row[2 * i2], v1 = row[2 * i2 + 1];
                float4 g0 = sG[2 * i2], g1v = sG[2 * i2 + 1];
                float4 b0 = sBe[2 * i2], b1v = sBe[2 * i2 + 1];
                float y0 = fmaxf(fmaf((v0.x - mu) * inv, g0.x, b0.x), 0.f);
                float y1 = fmaxf(fmaf((v0.y - mu) * inv, g0.y, b0.y), 0.f);
                float y2 = fmaxf(fmaf((v0.z - mu) * inv, g0.z, b0.z), 0.f);
                float y3 = fmaxf(fmaf((v0.w - mu) * inv, g0.w, b0.w), 0.f);
                float y4 = fmaxf(fmaf((v1.x - mu) * inv, g1v.x, b1v.x), 0.f);
                float y5 = fmaxf(fmaf((v1.y - mu) * inv, g1v.y, b1v.y), 0.f);
                float y6 = fmaxf(fmaf((v1.z - mu) * inv, g1v.z, b1v.z), 0.f);
                float y7 = fmaxf(fmaf((v1.w - mu) * inv, g1v.w, b1v.w), 0.f);
                uint4 p;
                p.x = pack_h2(y0, y1); p.y = pack_h2(y2, y3);
                p.z = pack_h2(y4, y5); p.w = pack_h2(y6, y7);
                op[i2] = p;
            }
        } else {
            const float4* sLw = (const float4*)(smf + 768 + h2 * 128);
            float dot = 0.f;
#pragma unroll
            for (int i = 0; i < 32; i++) {
                float4 v = row[i], g = sG[i], be = sBe[i], w = sLw[i];
                dot = fmaf(fmaxf(fmaf((v.x - mu) * inv, g.x, be.x), 0.f), w.x, dot);
                dot = fmaf(fmaxf(fmaf((v.y - mu) * inv, g.y, be.y), 0.f), w.y, dot);
                dot = fmaf(fmaxf(fmaf((v.z - mu) * inv, g.z, be.z), 0.f), w.z, dot);
                dot = fmaf(fmaxf(fmaf((v.w - mu) * inv, g.w, be.w), 0.f), w.w, dot);
            }
            dot += __shfl_xor_sync(0xffffffffu, dot, 1);
            if (h2 == 0) outDur[m0 + r] = fmaxf(dot + lb[0], 0.f);
        }
    }

    // conv1: publish tile completion
    if (!isC2) {
        __syncthreads();
        if (tid == 0) {
            __threadfence();
            atomicExch(&g_flag[tile], 1);
        }
    }
}

// ---------------------------------------------------------------------------
// Per-batch cumsum of target + searchsorted(right) -> g_idx[b,t] (-1 = zero)
// ---------------------------------------------------------------------------
__global__ void scan_idx(const int* __restrict__ target) {
    __shared__ int cum[LL];
    __shared__ int ps[256];
    int b = blockIdx.x;
    int tid = threadIdx.x;
    const int* tb = target + b * LL;
    int v[4], s = 0;
#pragma unroll
    for (int i = 0; i < 4; i++) { v[i] = tb[tid * 4 + i]; s += v[i]; }
    ps[tid] = s;
    __syncthreads();
    for (int o = 1; o < 256; o <<= 1) {
        int t = (tid >= o) ? ps[tid - o] : 0;
        __syncthreads();
        ps[tid] += t;
        __syncthreads();
    }
    int run = ps[tid] - s;
#pragma unroll
    for (int i = 0; i < 4; i++) { run += v[i]; cum[tid * 4 + i] = run; }
    __syncthreads();
    int total = cum[LL - 1];
    for (int t = tid; t < TT; t += 256) {
        int r = -1;
        if (t < total) {
            int lo = 0, hi = LL;
            while (lo < hi) {
                int mid = (lo + hi) >> 1;
                if (cum[mid] <= t) lo = mid + 1; else hi = mid;
            }
            r = lo < (LL - 1) ? lo : (LL - 1);
        }
        g_idx[b * TT + t] = r;
    }
}

// ---------------------------------------------------------------------------
// Gather/zero-fill: out[b,t,:] = (idx>=0) ? x[b,idx,:] : 0
// Grid-stride, 4 rows/block/iter, streaming stores, unroll-4 for MLP.
// ---------------------------------------------------------------------------
__global__ void copy_out(const float* __restrict__ X, float* __restrict__ out) {
    int tid  = threadIdx.x;
    int lane = tid & 63;
    int r0   = blockIdx.x * 4 + (tid >> 6);
#pragma unroll 4
    for (int it = 0; it < (BB * TT) / (CO_GRID * 4); it++) {
        int rt = r0 + it * (CO_GRID * 4);
        int b = rt >> 13;
        int j = g_idx[rt];
        float4 val = make_float4(0.f, 0.f, 0.f, 0.f);
        if (j >= 0)
            val = __ldg(reinterpret_cast<const float4*>(
                            X + (size_t)(b * LL + j) * EE) + lane);
        __stcs(reinterpret_cast<float4*>(out + (size_t)rt * EE) + lane, val);
    }
}

// ---------------------------------------------------------------------------
extern "C" void kernel_launch(void* const* d_in, const int* in_sizes, int n_in,
                              void* d_out, int out_size) {
    const float* x      = (const float*)d_in[0];
    const int*   target = (const int*)  d_in[1];
    const float* c1w = (const float*)d_in[3];
    const float* c1b = (const float*)d_in[4];
    const float* g1  = (const float*)d_in[5];
    const float* b1  = (const float*)d_in[6];
    const float* c2w = (const float*)d_in[7];
    const float* c2b = (const float*)d_in[8];
    const float* g2  = (const float*)d_in[9];
    const float* b2  = (const float*)d_in[10];
    const float* lw  = (const float*)d_in[11];
    const float* lb  = (const float*)d_in[12];

    float* out = (float*)d_out;
    float* dur = out + OUT_OFF;

    __half *B1, *B2;
    cudaGetSymbolAddress((void**)&B1, g_B1);
    cudaGetSymbolAddress((void**)&B2, g_B2);

    cudaFuncSetAttribute(conv_fused, cudaFuncAttributeMaxDynamicSharedMemorySize,
                         SMEM_BYTES);

    // Streams + events for fork/join inside graph capture.
    static cudaStream_t s_side = nullptr, s_pre = nullptr;
    static cudaEvent_t  ev_fork = nullptr, ev_px = nullptr, ev_join = nullptr;
    if (s_side == nullptr) {
        cudaStreamCreateWithFlags(&s_side, cudaStreamNonBlocking);
        cudaStreamCreateWithFlags(&s_pre,  cudaStreamNonBlocking);
        cudaEventCreateWithFlags(&ev_fork, cudaEventDisableTiming);
        cudaEventCreateWithFlags(&ev_px,   cudaEventDisableTiming);
        cudaEventCreateWithFlags(&ev_join, cudaEventDisableTiming);
    }

    cudaEventRecord(ev_fork, 0);
    cudaStreamWaitEvent(s_side, ev_fork, 0);
    cudaStreamWaitEvent(s_pre,  ev_fork, 0);

    // s_pre: prep_x (gates conv1 A reads)
    prep_x<<<MM * EE / 4 / 256, 256, 0, s_pre>>>(x);
    cudaEventRecord(ev_px, s_pre);

    // s_side: regulate path only (scan -> gather)
    scan_idx<<<BB, 256, 0, s_side>>>(target);
    copy_out<<<CO_GRID, 256, 0, s_side>>>(x, out);
    cudaEventRecord(ev_join, s_side);

    // main: both weight preps (coalesced, cheap), then fused convs
    prep_w<<<KD, 256>>>(c1w, B1, 1);
    prep_w<<<KD, 256>>>(c2w, B2, 0);
    cudaStreamWaitEvent(0, ev_px, 0);
    conv_fused<<<2 * NTILES, 256, SMEM_BYTES>>>(c1b, g1, b1, c2b, g2, b2,
                                                lw, lb, dur);

    // join
    cudaStreamWaitEvent(0, ev_join, 0);
}